// round 7
// baseline (speedup 1.0000x reference)
#include <cuda_runtime.h>
#include <cuda_bf16.h>
#include <cstdint>

using bf16 = __nv_bfloat16;

#define BSZ 2
#define SEQ 2048
#define HID 1024
#define NS  4
#define H   256

// ---------------- device scratch ----------------
__device__ __align__(256) bf16 g_hidH [BSZ*SEQ*HID];
__device__ __align__(256) bf16 g_hidL [BSZ*SEQ*HID];
__device__ __align__(256) bf16 g_hidTH[BSZ*HID*SEQ];
__device__ __align__(256) bf16 g_hidTL[BSZ*HID*SEQ];
__device__ __align__(256) bf16 g_qH   [NS*H*HID];
__device__ __align__(256) bf16 g_qL   [NS*H*HID];
__device__ __align__(256) bf16 g_cTH  [NS*H*HID];
__device__ __align__(256) bf16 g_cTL  [NS*H*HID];
__device__ __align__(256) float g_Pf  [8*H*H];      // Xh^T Xh
__device__ __align__(256) float g_Qf  [8*H*H];      // Xh^T Xl
__device__ __align__(256) bf16 g_KH   [8*H*H];
__device__ __align__(256) bf16 g_KL   [8*H*H];
__device__ __align__(256) float g_tmpf[8*H*HID];    // p2 split-K accumulation
__device__ __align__(256) bf16 g_tmpH [8*H*HID];
__device__ __align__(256) bf16 g_tmpL [8*H*HID];
__device__ __align__(256) float g_Mf  [8*H*H];      // M^T
__device__ __align__(256) bf16 g_MH   [8*H*H];
__device__ __align__(256) bf16 g_ML   [8*H*H];

// ---------------- helpers ----------------
__device__ __forceinline__ void split2(float v, bf16& h, bf16& l) {
    h = __float2bfloat16_rn(v);
    l = __float2bfloat16_rn(v - __bfloat162float(h));
}
__device__ __forceinline__ uint32_t smem_u32(const void* p) {
    uint32_t a;
    asm("{ .reg .u64 t; cvta.to.shared.u64 t, %1; cvt.u32.u64 %0, t; }" : "=r"(a) : "l"(p));
    return a;
}
__device__ __forceinline__ void cpa(uint32_t dst, const void* src) {
    asm volatile("cp.async.cg.shared.global [%0], [%1], 16;" :: "r"(dst), "l"(src));
}
__device__ __forceinline__ void ldsm4(uint32_t (&r)[4], uint32_t addr) {
    asm volatile("ldmatrix.sync.aligned.m8n8.x4.shared.b16 {%0,%1,%2,%3}, [%4];"
        : "=r"(r[0]), "=r"(r[1]), "=r"(r[2]), "=r"(r[3]) : "r"(addr));
}
__device__ __forceinline__ void mma16816(float (&d)[4], const uint32_t (&a)[4],
                                         uint32_t b0, uint32_t b1) {
    asm volatile("mma.sync.aligned.m16n8k16.row.col.f32.bf16.bf16.f32 "
        "{%0,%1,%2,%3}, {%4,%5,%6,%7}, {%8,%9}, {%0,%1,%2,%3};"
        : "+f"(d[0]), "+f"(d[1]), "+f"(d[2]), "+f"(d[3])
        : "r"(a[0]), "r"(a[1]), "r"(a[2]), "r"(a[3]), "r"(b0), "r"(b1));
}
__device__ __forceinline__ uint32_t swz(int row, int c) {
    return (uint32_t)(row * 64 + ((c ^ ((row >> 1) & 3)) << 4));
}

// Stage layout: A[128x32] (+AL), B[128x32] (+BL)
template<int NPROD> struct Lay {
    static constexpr uint32_t AL = 8192u;
    static constexpr uint32_t BH = (NPROD == 3) ? 16384u : 8192u;
    static constexpr uint32_t BL = BH + 8192u;
    static constexpr uint32_t STAGE = (NPROD == 3) ? 32768u : 16384u;
};

template<int NPROD>
__device__ __forceinline__ void load_stage(uint32_t sb,
        const bf16* __restrict__ AH, const bf16* __restrict__ AL, int lda,
        const bf16* __restrict__ BH, const bf16* __restrict__ BL, int ldb, int k0) {
    using L = Lay<NPROD>;
    int tid = threadIdx.x;
    #pragma unroll
    for (int t = 0; t < 2; ++t) {
        int cid = tid + t * 256;
        int row = cid >> 2, c = cid & 3;
        uint32_t so = swz(row, c);
        size_t oa = (size_t)row * lda + k0 + c * 8;
        size_t ob = (size_t)row * ldb + k0 + c * 8;
        cpa(sb + so,         AH + oa);
        cpa(sb + L::BH + so, BH + ob);
        if (NPROD == 3) {
            cpa(sb + L::AL + so, AL + oa);
            cpa(sb + L::BL + so, BL + ob);
        }
    }
    asm volatile("cp.async.commit_group;" ::: "memory");
}

// C[128,128] = A[128,K] * B[128,K]^T.  NPROD=3: AhBh+AhBl+AlBh; NPROD=1: AhBh.
// EPI: 0 = atomicAdd fp32, 1 = store fp32
template<int EPI, int NPROD>
__device__ void gemm_mma(const bf16* AH, const bf16* AL, int lda,
                         const bf16* BH, const bf16* BL, int ldb, int kIters,
                         float* Cf, int ldc) {
    using L = Lay<NPROD>;
    extern __shared__ char smem[];
    const uint32_t sbase = smem_u32(smem);
    const int tid = threadIdx.x, lane = tid & 31, wid = tid >> 5;
    const int wm = wid & 1, wn = wid >> 1;

    float acc[4][4][4];
    #pragma unroll
    for (int i = 0; i < 4; ++i)
        #pragma unroll
        for (int j = 0; j < 4; ++j)
            #pragma unroll
            for (int v = 0; v < 4; ++v) acc[i][j][v] = 0.f;

    load_stage<NPROD>(sbase,            AH, AL, lda, BH, BL, ldb, 0);
    load_stage<NPROD>(sbase + L::STAGE, AH, AL, lda, BH, BL, ldb, 32);

    const int mi = lane >> 3, lr = lane & 7;
    const int rA0 = wm * 64 + (mi & 1) * 8 + lr;
    const int rB0 = wn * 32 + (mi & 1) * 8 + lr;
    const int chb = mi >> 1;
    const int kkst = wid & 1;          // warp-parity stagger

    for (int it = 0; it < kIters; ++it) {
        if (it + 1 < kIters)
            asm volatile("cp.async.wait_group 1;" ::: "memory");
        else
            asm volatile("cp.async.wait_group 0;" ::: "memory");
        __syncthreads();

        uint32_t sb = sbase + (uint32_t)(it % 3) * L::STAGE;
        if (it + 2 < kIters)
            load_stage<NPROD>(sbase + (uint32_t)((it + 2) % 3) * L::STAGE,
                              AH, AL, lda, BH, BL, ldb, (it + 2) * 32);

        #pragma unroll
        for (int t = 0; t < 2; ++t) {
            int kk = t ^ kkst;
            int c = kk * 2 + chb;
            uint32_t ah[4][4], al[4][4], bh[2][4], bl[2][4];
            #pragma unroll
            for (int j = 0; j < 2; ++j) {
                int r = rB0 + j * 16;
                uint32_t so = swz(r, c);
                ldsm4(bh[j], sb + L::BH + so);
                if (NPROD == 3) ldsm4(bl[j], sb + L::BL + so);
            }
            #pragma unroll
            for (int i = 0; i < 4; ++i) {
                int r = rA0 + i * 16;
                uint32_t so = swz(r, c);
                ldsm4(ah[i], sb + so);
                if (NPROD == 3) ldsm4(al[i], sb + L::AL + so);
            }
            #pragma unroll
            for (int i = 0; i < 4; ++i)
                #pragma unroll
                for (int j = 0; j < 4; ++j) {
                    int j2 = j >> 1, jo = j & 1;
                    mma16816(acc[i][j], ah[i], bh[j2][jo], bh[j2][jo + 2]);
                    if (NPROD == 3) {
                        mma16816(acc[i][j], ah[i], bl[j2][jo], bl[j2][jo + 2]);
                        mma16816(acc[i][j], al[i], bh[j2][jo], bh[j2][jo + 2]);
                    }
                }
        }
    }

    #pragma unroll
    for (int i = 0; i < 4; ++i)
        #pragma unroll
        for (int j = 0; j < 4; ++j) {
            int r   = wm * 64 + i * 16 + (lane >> 2);
            int col = wn * 32 + j * 8 + (lane & 3) * 2;
            if (EPI == 0) {
                atomicAdd(Cf + (size_t)r * ldc + col,           acc[i][j][0]);
                atomicAdd(Cf + (size_t)r * ldc + col + 1,       acc[i][j][1]);
                atomicAdd(Cf + (size_t)(r + 8) * ldc + col,     acc[i][j][2]);
                atomicAdd(Cf + (size_t)(r + 8) * ldc + col + 1, acc[i][j][3]);
            } else {
                *reinterpret_cast<float2*>(Cf + (size_t)r * ldc + col) =
                    make_float2(acc[i][j][0], acc[i][j][1]);
                *reinterpret_cast<float2*>(Cf + (size_t)(r + 8) * ldc + col) =
                    make_float2(acc[i][j][2], acc[i][j][3]);
            }
        }
}

// ---- pass wrappers ----
// P = Xh^T Xh (sel 0), Q = Xh^T Xl (sel 1); split-K over t in 4 chunks of 512
__global__ void __launch_bounds__(256, 2) k_p1() {
    int z = blockIdx.z;
    int sel = z >> 5, w = z & 31, pair = w >> 2, split = w & 3;
    int b = pair >> 2, q = pair & 3;
    size_t base = ((size_t)b * HID + q * H) * SEQ + split * 512;
    int m0 = blockIdx.x * 128, n0 = blockIdx.y * 128;
    const bf16* A  = g_hidTH + base + (size_t)m0 * SEQ;
    const bf16* Bh = (sel ? g_hidTL : g_hidTH) + base + (size_t)n0 * SEQ;
    float* dst = (sel ? g_Qf : g_Pf) + (size_t)pair * H * H + m0 * H + n0;
    gemm_mma<0, 1>(A, nullptr, SEQ, Bh, nullptr, SEQ, 16, dst, H);
}
// K = P + Q + Q^T, split into KH/KL
__global__ void __launch_bounds__(256) k_combK() {
    __shared__ float sh[32][33];
    int pair = blockIdx.z, it = blockIdx.y, jt = blockIdx.x;
    int tx = threadIdx.x & 31, ty = threadIdx.x >> 5;
    const float* P = g_Pf + (size_t)pair * H * H;
    const float* Q = g_Qf + (size_t)pair * H * H;
    #pragma unroll
    for (int i = 0; i < 4; ++i) {
        int r = ty + i * 8;
        sh[r][tx] = Q[(size_t)(jt * 32 + r) * H + it * 32 + tx];
    }
    __syncthreads();
    #pragma unroll
    for (int i = 0; i < 4; ++i) {
        int r = ty + i * 8;
        int row = it * 32 + r, col = jt * 32 + tx;
        size_t idx = (size_t)pair * H * H + (size_t)row * H + col;
        float v = P[(size_t)row * H + col] + Q[(size_t)row * H + col] + sh[tx][r];
        bf16 h, l; split2(v, h, l);
        g_KH[idx] = h; g_KL[idx] = l;
    }
}
// p2: tmpf = qw * K (K symmetric), split-K x2 over f
__global__ void __launch_bounds__(256, 2) k_p2() {
    int z = blockIdx.z;                 // ((b*4+a)*4+q)*2 + split
    int split = z & 1, g = z >> 1;
    int b = g >> 4, a = (g >> 2) & 3, q = g & 3;
    int m0 = blockIdx.x * 128, n0 = blockIdx.y * 128;
    size_t ab = (size_t)a * H * HID + (size_t)m0 * HID + q * H + split * 128;
    size_t bb = (size_t)((b << 2) | q) * H * H + (size_t)n0 * H + split * 128;
    size_t cb = (size_t)((b << 2) | a) * H * HID + (size_t)m0 * HID + q * H + n0;
    gemm_mma<0, 3>(g_qH + ab, g_qL + ab, HID, g_KH + bb, g_KL + bb, H,
                   4, g_tmpf + cb, HID);
}
// split tmpf -> tmpH/tmpL
__global__ void __launch_bounds__(256) k_splitT() {
    size_t i = (size_t)blockIdx.x * 2048 + threadIdx.x * 8;
    #pragma unroll
    for (int j = 0; j < 8; ++j) {
        bf16 h, l; split2(g_tmpf[i + j], h, l);
        g_tmpH[i + j] = h; g_tmpL[i + j] = l;
    }
}
// p3: M^T = cT * tmp^T, split-K x8
__global__ void __launch_bounds__(256, 2) k_p3() {
    int z = blockIdx.z, pair = z >> 3, split = z & 7;
    int a = pair & 3;
    int m0 = blockIdx.x * 128, n0 = blockIdx.y * 128;
    size_t ab = (size_t)a * H * HID + (size_t)m0 * HID + split * 128;
    size_t bb = (size_t)pair * H * HID + (size_t)n0 * HID + split * 128;
    gemm_mma<0, 3>(g_cTH + ab, g_cTL + ab, HID, g_tmpH + bb, g_tmpL + bb, HID,
                   4, g_Mf + (size_t)pair * H * H + m0 * H + n0, H);
}
// p4: out = hid * M
__global__ void __launch_bounds__(256, 2) k_p4(float* __restrict__ out) {
    int pair = blockIdx.z, b = pair >> 2, a = pair & 3;
    int m0 = blockIdx.x * 128, n0 = blockIdx.y * 128;
    size_t ab = (size_t)b * SEQ * HID + (size_t)m0 * HID + a * H;
    size_t bb = (size_t)pair * H * H + (size_t)n0 * H;
    gemm_mma<1, 3>(g_hidH + ab, g_hidL + ab, HID, g_MH + bb, g_ML + bb, H,
                   8, out + ab + n0, HID);
}

// ---- merged prep ----
__global__ void __launch_bounds__(256) k_prep(const float* __restrict__ hid,
                                              const float* __restrict__ q,
                                              const float* __restrict__ c) {
    __shared__ bf16 shH[32][33], shL[32][33];
    int blk = blockIdx.x, tid = threadIdx.x;
    if (blk < 4096) {
        int b = blk >> 11, tt = (blk >> 5) & 63, ft = blk & 31;
        int tx = tid & 31, ty = tid >> 5;
        int t0 = tt * 32, f0 = ft * 32;
        #pragma unroll
        for (int i = 0; i < 4; ++i) {
            int r = ty + i * 8;
            size_t idx = ((size_t)b * SEQ + t0 + r) * HID + f0 + tx;
            float v = hid[idx];
            bf16 h, l; split2(v, h, l);
            g_hidH[idx] = h; g_hidL[idx] = l;
            shH[r][tx] = h; shL[r][tx] = l;
        }
        __syncthreads();
        #pragma unroll
        for (int i = 0; i < 4; ++i) {
            int r = ty + i * 8;
            size_t idx = ((size_t)b * HID + f0 + r) * SEQ + t0 + tx;
            g_hidTH[idx] = shH[tx][r];
            g_hidTL[idx] = shL[tx][r];
        }
    } else if (blk < 5120) {
        size_t i = (size_t)(blk - 4096) * 1024 + tid * 4;
        float4 v = *reinterpret_cast<const float4*>(q + i);
        bf16 h, l;
        split2(v.x, h, l); g_qH[i] = h;   g_qL[i] = l;
        split2(v.y, h, l); g_qH[i+1] = h; g_qL[i+1] = l;
        split2(v.z, h, l); g_qH[i+2] = h; g_qL[i+2] = l;
        split2(v.w, h, l); g_qH[i+3] = h; g_qL[i+3] = l;
    } else if (blk < 6144) {
        int z = blk - 5120;
        int a = z >> 8, kt = (z >> 3) & 31, gt = z & 7;
        int tx = tid & 31, ty = tid >> 5;
        int k0 = kt * 32, g0 = gt * 32;
        #pragma unroll
        for (int i = 0; i < 4; ++i) {
            int r = ty + i * 8;
            float v = c[((size_t)a * HID + k0 + r) * H + g0 + tx];
            bf16 h, l; split2(v, h, l);
            shH[r][tx] = h; shL[r][tx] = l;
        }
        __syncthreads();
        #pragma unroll
        for (int i = 0; i < 4; ++i) {
            int r = ty + i * 8;
            size_t idx = ((size_t)a * H + g0 + r) * HID + k0 + tx;
            g_cTH[idx] = shH[tx][r];
            g_cTL[idx] = shL[tx][r];
        }
    } else {
        int z = blk - 6144;                 // 0..895 : zero Pf, Qf, Mf, tmpf
        float* dst;
        size_t base;
        if (z < 128)      { dst = g_Pf;   base = (size_t)z * 4096; }
        else if (z < 256) { dst = g_Qf;   base = (size_t)(z - 128) * 4096; }
        else if (z < 384) { dst = g_Mf;   base = (size_t)(z - 256) * 4096; }
        else              { dst = g_tmpf; base = (size_t)(z - 384) * 4096; }
        base += tid * 16;
        float4 zv = make_float4(0.f, 0.f, 0.f, 0.f);
        #pragma unroll
        for (int i = 0; i < 4; ++i)
            *reinterpret_cast<float4*>(dst + base + i * 4) = zv;
    }
}
__global__ void __launch_bounds__(256) k_splitM() {
    size_t i = (size_t)blockIdx.x * 2048 + threadIdx.x * 8;
    #pragma unroll
    for (int j = 0; j < 8; ++j) {
        bf16 h, l; split2(g_Mf[i + j], h, l);
        g_MH[i + j] = h; g_ML[i + j] = l;
    }
}

extern "C" void kernel_launch(void* const* d_in, const int* in_sizes, int n_in,
                              void* d_out, int out_size) {
    const float* hidden    = (const float*)d_in[0];
    const float* queries   = (const float*)d_in[1];
    const float* combiners = (const float*)d_in[2];
    float* out = (float*)d_out;

    cudaFuncSetAttribute(k_p1, cudaFuncAttributeMaxDynamicSharedMemorySize, 49152);
    cudaFuncSetAttribute(k_p2, cudaFuncAttributeMaxDynamicSharedMemorySize, 98304);
    cudaFuncSetAttribute(k_p3, cudaFuncAttributeMaxDynamicSharedMemorySize, 98304);
    cudaFuncSetAttribute(k_p4, cudaFuncAttributeMaxDynamicSharedMemorySize, 98304);

    k_prep<<<7040, 256>>>(hidden, queries, combiners);
    k_p1<<<dim3(2, 2, 64), 256, 49152>>>();
    k_combK<<<dim3(8, 8, 8), 256>>>();
    k_p2<<<dim3(2, 2, 64), 256, 98304>>>();
    k_splitT<<<1024, 256>>>();
    k_p3<<<dim3(2, 2, 64), 256, 98304>>>();
    k_splitM<<<256, 256>>>();
    k_p4<<<dim3(16, 2, 8), 256, 98304>>>(out);
}

// round 8
// speedup vs baseline: 1.3858x; 1.3858x over previous
#include <cuda_runtime.h>
#include <cuda_fp16.h>
#include <cstdint>

#define BSZ 2
#define SEQ 2048
#define HID 1024
#define NS  4
#define H   256

// ---------------- device scratch ----------------
__device__ __align__(256) __half g_hidH [BSZ*SEQ*HID];   // hidden hi, row-major
__device__ __align__(256) __half g_hidTH[BSZ*HID*SEQ];   // hidden hi, transposed
__device__ __align__(256) __half g_hidTL[BSZ*HID*SEQ];   // hidden lo, transposed
__device__ __align__(256) __half g_qH   [NS*H*HID];      // queries hi
__device__ __align__(256) __half g_cTH  [NS*H*HID];      // combiners^T hi
__device__ __align__(256) float  g_Pf   [8*H*H];         // Xh^T Xh
__device__ __align__(256) float  g_Qf   [8*H*H];         // Xh^T Xl
__device__ __align__(256) __half g_KH   [8*H*H];
__device__ __align__(256) __half g_KL   [8*H*H];
__device__ __align__(256) __half g_tmpH [8*H*HID];
__device__ __align__(256) __half g_tmpL [8*H*HID];
__device__ __align__(256) float  g_Mf   [8*H*H];         // M^T
__device__ __align__(256) __half g_MH   [8*H*H];
__device__ __align__(256) __half g_ML   [8*H*H];

// ---------------- helpers ----------------
__device__ __forceinline__ void split2h(float v, __half& h, __half& l) {
    h = __float2half_rn(v);
    l = __float2half_rn(v - __half2float(h));
}
__device__ __forceinline__ uint32_t smem_u32(const void* p) {
    uint32_t a;
    asm("{ .reg .u64 t; cvta.to.shared.u64 t, %1; cvt.u32.u64 %0, t; }" : "=r"(a) : "l"(p));
    return a;
}
__device__ __forceinline__ void cpa(uint32_t dst, const void* src) {
    asm volatile("cp.async.cg.shared.global [%0], [%1], 16;" :: "r"(dst), "l"(src));
}
__device__ __forceinline__ void ldsm4(uint32_t (&r)[4], uint32_t addr) {
    asm volatile("ldmatrix.sync.aligned.m8n8.x4.shared.b16 {%0,%1,%2,%3}, [%4];"
        : "=r"(r[0]), "=r"(r[1]), "=r"(r[2]), "=r"(r[3]) : "r"(addr));
}
__device__ __forceinline__ void mma16816(float (&d)[4], const uint32_t (&a)[4],
                                         uint32_t b0, uint32_t b1) {
    asm volatile("mma.sync.aligned.m16n8k16.row.col.f32.f16.f16.f32 "
        "{%0,%1,%2,%3}, {%4,%5,%6,%7}, {%8,%9}, {%0,%1,%2,%3};"
        : "+f"(d[0]), "+f"(d[1]), "+f"(d[2]), "+f"(d[3])
        : "r"(a[0]), "r"(a[1]), "r"(a[2]), "r"(a[3]), "r"(b0), "r"(b1));
}
__device__ __forceinline__ uint32_t swz(int row, int c) {
    return (uint32_t)(row * 64 + ((c ^ ((row >> 1) & 3)) << 4));
}

// Stage layout: Ah[128x32] @0 (8KB), Bh[NTILE x 32] @8K, Bl after (if BPROD==2)
template<int BPROD, int NTILE> struct Lay {
    static constexpr uint32_t BH = 8192u;
    static constexpr uint32_t BN = (NTILE == 128) ? 8192u : 4096u;
    static constexpr uint32_t BL = BH + BN;
    static constexpr uint32_t STAGE = BH + BN * BPROD;
};

template<int BPROD, int NTILE>
__device__ __forceinline__ void load_stage(uint32_t sb,
        const __half* __restrict__ Ah, int lda,
        const __half* __restrict__ Bh, const __half* __restrict__ Bl,
        int ldb, int k0) {
    using L = Lay<BPROD, NTILE>;
    int tid = threadIdx.x;
    #pragma unroll
    for (int t = 0; t < 2; ++t) {
        int cid = tid + t * 256;
        int row = cid >> 2, c = cid & 3;
        uint32_t so = swz(row, c);
        cpa(sb + so, Ah + (size_t)row * lda + k0 + c * 8);
    }
    if (NTILE == 128) {
        #pragma unroll
        for (int t = 0; t < 2; ++t) {
            int cid = tid + t * 256;
            int row = cid >> 2, c = cid & 3;
            uint32_t so = swz(row, c);
            size_t ob = (size_t)row * ldb + k0 + c * 8;
            cpa(sb + L::BH + so, Bh + ob);
            if (BPROD == 2) cpa(sb + L::BL + so, Bl + ob);
        }
    } else {
        int row = tid >> 2, c = tid & 3;
        uint32_t so = swz(row, c);
        size_t ob = (size_t)row * ldb + k0 + c * 8;
        cpa(sb + L::BH + so, Bh + ob);
        if (BPROD == 2) cpa(sb + L::BL + so, Bl + ob);
    }
    asm volatile("cp.async.commit_group;" ::: "memory");
}

// C[128,NTILE] = Ah[128,K] * (Bh + Bl)[NTILE,K]^T   (fp16, fp32 accum)
// EPI: 0 = atomicAdd fp32, 1 = store fp32, 2 = split-store fp16 H/L
template<int EPI, int BPROD, int NTILE>
__device__ void gemm_mma(const __half* Ah, int lda,
                         const __half* Bh, const __half* Bl, int ldb, int kIters,
                         float* Cf, __half* CH, __half* CL, int ldc) {
    using L = Lay<BPROD, NTILE>;
    constexpr int MI = (NTILE == 128) ? 4 : 2;
    extern __shared__ char smem[];
    const uint32_t sbase = smem_u32(smem);
    const int tid = threadIdx.x, lane = tid & 31, wid = tid >> 5;
    const int wm = (NTILE == 128) ? (wid & 1) : (wid & 3);
    const int wn = (NTILE == 128) ? (wid >> 1) : (wid >> 2);

    float acc[MI][4][4];
    #pragma unroll
    for (int i = 0; i < MI; ++i)
        #pragma unroll
        for (int j = 0; j < 4; ++j)
            #pragma unroll
            for (int v = 0; v < 4; ++v) acc[i][j][v] = 0.f;

    load_stage<BPROD, NTILE>(sbase,            Ah, lda, Bh, Bl, ldb, 0);
    load_stage<BPROD, NTILE>(sbase + L::STAGE, Ah, lda, Bh, Bl, ldb, 32);

    const int mi = lane >> 3, lr = lane & 7;
    const int rA0 = wm * (MI * 16) + (mi & 1) * 8 + lr;
    const int rB0 = wn * 32 + (mi & 1) * 8 + lr;
    const int chb = mi >> 1;

    for (int it = 0; it < kIters; ++it) {
        if (it + 1 < kIters)
            asm volatile("cp.async.wait_group 1;" ::: "memory");
        else
            asm volatile("cp.async.wait_group 0;" ::: "memory");
        __syncthreads();

        uint32_t sb = sbase + (uint32_t)(it % 3) * L::STAGE;
        if (it + 2 < kIters)
            load_stage<BPROD, NTILE>(sbase + (uint32_t)((it + 2) % 3) * L::STAGE,
                                     Ah, lda, Bh, Bl, ldb, (it + 2) * 32);

        #pragma unroll
        for (int kk = 0; kk < 2; ++kk) {
            int c = kk * 2 + chb;
            uint32_t a[MI][4], bh[2][4], bl[2][4];
            #pragma unroll
            for (int j = 0; j < 2; ++j) {
                int r = rB0 + j * 16;
                uint32_t so = swz(r, c);
                ldsm4(bh[j], sb + L::BH + so);
                if (BPROD == 2) ldsm4(bl[j], sb + L::BL + so);
            }
            #pragma unroll
            for (int i = 0; i < MI; ++i) {
                int r = rA0 + i * 16;
                ldsm4(a[i], sb + swz(r, c));
            }
            #pragma unroll
            for (int i = 0; i < MI; ++i)
                #pragma unroll
                for (int j = 0; j < 4; ++j) {
                    int j2 = j >> 1, jo = j & 1;
                    mma16816(acc[i][j], a[i], bh[j2][jo], bh[j2][jo + 2]);
                    if (BPROD == 2)
                        mma16816(acc[i][j], a[i], bl[j2][jo], bl[j2][jo + 2]);
                }
        }
    }

    #pragma unroll
    for (int i = 0; i < MI; ++i)
        #pragma unroll
        for (int j = 0; j < 4; ++j) {
            int r   = wm * (MI * 16) + i * 16 + (lane >> 2);
            int col = wn * 32 + j * 8 + (lane & 3) * 2;
            if (EPI == 0) {
                atomicAdd(Cf + (size_t)r * ldc + col,           acc[i][j][0]);
                atomicAdd(Cf + (size_t)r * ldc + col + 1,       acc[i][j][1]);
                atomicAdd(Cf + (size_t)(r + 8) * ldc + col,     acc[i][j][2]);
                atomicAdd(Cf + (size_t)(r + 8) * ldc + col + 1, acc[i][j][3]);
            } else if (EPI == 1) {
                *reinterpret_cast<float2*>(Cf + (size_t)r * ldc + col) =
                    make_float2(acc[i][j][0], acc[i][j][1]);
                *reinterpret_cast<float2*>(Cf + (size_t)(r + 8) * ldc + col) =
                    make_float2(acc[i][j][2], acc[i][j][3]);
            } else {
                __half h0, l0, h1, l1;
                __half2 ph, pl;
                split2h(acc[i][j][0], h0, l0); split2h(acc[i][j][1], h1, l1);
                ph.x = h0; ph.y = h1; pl.x = l0; pl.y = l1;
                *reinterpret_cast<__half2*>(CH + (size_t)r * ldc + col) = ph;
                *reinterpret_cast<__half2*>(CL + (size_t)r * ldc + col) = pl;
                split2h(acc[i][j][2], h0, l0); split2h(acc[i][j][3], h1, l1);
                ph.x = h0; ph.y = h1; pl.x = l0; pl.y = l1;
                *reinterpret_cast<__half2*>(CH + (size_t)(r + 8) * ldc + col) = ph;
                *reinterpret_cast<__half2*>(CL + (size_t)(r + 8) * ldc + col) = pl;
            }
        }
}

// ---- pass wrappers ----
// P = Xh^T Xh (sel 0), Q = Xh^T Xl (sel 1); split-K over t in 4 chunks of 512
__global__ void __launch_bounds__(256, 2) k_p1() {
    int z = blockIdx.z;
    int sel = z >> 5, w = z & 31, pair = w >> 2, split = w & 3;
    int b = pair >> 2, q = pair & 3;
    size_t base = ((size_t)b * HID + q * H) * SEQ + split * 512;
    int m0 = blockIdx.x * 128, n0 = blockIdx.y * 128;
    const __half* A  = g_hidTH + base + (size_t)m0 * SEQ;
    const __half* Bh = (sel ? g_hidTL : g_hidTH) + base + (size_t)n0 * SEQ;
    float* dst = (sel ? g_Qf : g_Pf) + (size_t)pair * H * H + m0 * H + n0;
    gemm_mma<0, 1, 128>(A, SEQ, Bh, nullptr, SEQ, 16, dst, nullptr, nullptr, H);
}
// K = P + Q + Q^T, split to fp16 KH/KL
__global__ void __launch_bounds__(256) k_combK() {
    __shared__ float sh[32][33];
    int pair = blockIdx.z, it = blockIdx.y, jt = blockIdx.x;
    int tx = threadIdx.x & 31, ty = threadIdx.x >> 5;
    const float* P = g_Pf + (size_t)pair * H * H;
    const float* Q = g_Qf + (size_t)pair * H * H;
    #pragma unroll
    for (int i = 0; i < 4; ++i) {
        int r = ty + i * 8;
        sh[r][tx] = Q[(size_t)(jt * 32 + r) * H + it * 32 + tx];
    }
    __syncthreads();
    #pragma unroll
    for (int i = 0; i < 4; ++i) {
        int r = ty + i * 8;
        int row = it * 32 + r, col = jt * 32 + tx;
        size_t idx = (size_t)pair * H * H + (size_t)row * H + col;
        float v = P[(size_t)row * H + col] + Q[(size_t)row * H + col] + sh[tx][r];
        __half h, l; split2h(v, h, l);
        g_KH[idx] = h; g_KL[idx] = l;
    }
}
// p2: tmp = qw_h * (Kh + Kl)  (K symmetric), direct split-store
__global__ void __launch_bounds__(256, 2) k_p2() {
    int z = blockIdx.z, b = z >> 4, a = (z >> 2) & 3, q = z & 3;
    int m0 = blockIdx.x * 128, n0 = blockIdx.y * 64;
    size_t ab = (size_t)a * H * HID + (size_t)m0 * HID + q * H;
    size_t bb = (size_t)((b << 2) | q) * H * H + (size_t)n0 * H;
    size_t cb = (size_t)((b << 2) | a) * H * HID + (size_t)m0 * HID + q * H + n0;
    gemm_mma<2, 2, 64>(g_qH + ab, HID, g_KH + bb, g_KL + bb, H,
                       8, nullptr, g_tmpH + cb, g_tmpL + cb, HID);
}
// p3: M^T = cT_h * (tmpH + tmpL)^T, split-K x4
__global__ void __launch_bounds__(256, 2) k_p3() {
    int z = blockIdx.z, pair = z >> 2, split = z & 3;
    int a = pair & 3;
    int m0 = blockIdx.x * 128, n0 = blockIdx.y * 64;
    size_t ab = (size_t)a * H * HID + (size_t)m0 * HID + split * 256;
    size_t bb = (size_t)pair * H * HID + (size_t)n0 * HID + split * 256;
    gemm_mma<0, 2, 64>(g_cTH + ab, HID, g_tmpH + bb, g_tmpL + bb, HID,
                       8, g_Mf + (size_t)pair * H * H + m0 * H + n0, nullptr, nullptr, H);
}
// split M^T -> MH/ML fp16
__global__ void __launch_bounds__(256) k_splitM() {
    size_t i = (size_t)blockIdx.x * 2048 + threadIdx.x * 8;
    #pragma unroll
    for (int j = 0; j < 8; ++j) {
        __half h, l; split2h(g_Mf[i + j], h, l);
        g_MH[i + j] = h; g_ML[i + j] = l;
    }
}
// p4: out = hid_h * (Mh + Ml)
__global__ void __launch_bounds__(256, 2) k_p4(float* __restrict__ out) {
    int pair = blockIdx.z, b = pair >> 2, a = pair & 3;
    int m0 = blockIdx.x * 128, n0 = blockIdx.y * 128;
    size_t ab = (size_t)b * SEQ * HID + (size_t)m0 * HID + a * H;
    size_t bb = (size_t)pair * H * H + (size_t)n0 * H;
    gemm_mma<1, 2, 128>(g_hidH + ab, HID, g_MH + bb, g_ML + bb, H,
                        8, out + ab + n0, nullptr, nullptr, HID);
}

// ---- merged prep ----
__global__ void __launch_bounds__(256) k_prep(const float* __restrict__ hid,
                                              const float* __restrict__ q,
                                              const float* __restrict__ c) {
    __shared__ __half shH[32][33], shL[32][33];
    int blk = blockIdx.x, tid = threadIdx.x;
    if (blk < 4096) {
        int b = blk >> 11, tt = (blk >> 5) & 63, ft = blk & 31;
        int tx = tid & 31, ty = tid >> 5;
        int t0 = tt * 32, f0 = ft * 32;
        #pragma unroll
        for (int i = 0; i < 4; ++i) {
            int r = ty + i * 8;
            size_t idx = ((size_t)b * SEQ + t0 + r) * HID + f0 + tx;
            float v = hid[idx];
            __half h, l; split2h(v, h, l);
            g_hidH[idx] = h;
            shH[r][tx] = h; shL[r][tx] = l;
        }
        __syncthreads();
        #pragma unroll
        for (int i = 0; i < 4; ++i) {
            int r = ty + i * 8;
            size_t idx = ((size_t)b * HID + f0 + r) * SEQ + t0 + tx;
            g_hidTH[idx] = shH[tx][r];
            g_hidTL[idx] = shL[tx][r];
        }
    } else if (blk < 5120) {
        size_t i = (size_t)(blk - 4096) * 1024 + tid * 4;
        float4 v = *reinterpret_cast<const float4*>(q + i);
        g_qH[i]   = __float2half_rn(v.x);
        g_qH[i+1] = __float2half_rn(v.y);
        g_qH[i+2] = __float2half_rn(v.z);
        g_qH[i+3] = __float2half_rn(v.w);
    } else if (blk < 6144) {
        int z = blk - 5120;
        int a = z >> 8, kt = (z >> 3) & 31, gt = z & 7;
        int tx = tid & 31, ty = tid >> 5;
        int k0 = kt * 32, g0 = gt * 32;
        #pragma unroll
        for (int i = 0; i < 4; ++i) {
            int r = ty + i * 8;
            shH[r][tx] = __float2half_rn(c[((size_t)a * HID + k0 + r) * H + g0 + tx]);
        }
        __syncthreads();
        #pragma unroll
        for (int i = 0; i < 4; ++i) {
            int r = ty + i * 8;
            g_cTH[((size_t)a * H + g0 + r) * HID + k0 + tx] = shH[tx][r];
        }
    } else {
        int z = blk - 6144;                 // 0..383 : zero Pf, Qf, Mf
        float* dst = (z < 128) ? g_Pf : ((z < 256) ? g_Qf : g_Mf);
        size_t base = (size_t)(z & 127) * 4096 + tid * 16;
        float4 zv = make_float4(0.f, 0.f, 0.f, 0.f);
        #pragma unroll
        for (int i = 0; i < 4; ++i)
            *reinterpret_cast<float4*>(dst + base + i * 4) = zv;
    }
}

extern "C" void kernel_launch(void* const* d_in, const int* in_sizes, int n_in,
                              void* d_out, int out_size) {
    const float* hidden    = (const float*)d_in[0];
    const float* queries   = (const float*)d_in[1];
    const float* combiners = (const float*)d_in[2];
    float* out = (float*)d_out;

    cudaFuncSetAttribute(k_p1, cudaFuncAttributeMaxDynamicSharedMemorySize, 49152);
    cudaFuncSetAttribute(k_p2, cudaFuncAttributeMaxDynamicSharedMemorySize, 49152);
    cudaFuncSetAttribute(k_p3, cudaFuncAttributeMaxDynamicSharedMemorySize, 49152);
    cudaFuncSetAttribute(k_p4, cudaFuncAttributeMaxDynamicSharedMemorySize, 73728);

    k_prep<<<6528, 256>>>(hidden, queries, combiners);
    k_p1<<<dim3(2, 2, 64), 256, 49152>>>();
    k_combK<<<dim3(8, 8, 8), 256>>>();
    k_p2<<<dim3(2, 4, 32), 256, 49152>>>();
    k_p3<<<dim3(2, 4, 32), 256, 49152>>>();
    k_splitM<<<256, 256>>>();
    k_p4<<<dim3(16, 2, 8), 256, 73728>>>(out);
}

// round 9
// speedup vs baseline: 1.5645x; 1.1290x over previous
#include <cuda_runtime.h>
#include <cuda_fp16.h>
#include <cstdint>

#define BSZ 2
#define SEQ 2048
#define HID 1024
#define NS  4
#define H   256

// ---------------- device scratch ----------------
__device__ __align__(256) __half g_hidH [BSZ*SEQ*HID];   // hidden hi, row-major
__device__ __align__(256) __half g_hidTH[BSZ*HID*SEQ];   // hidden hi, transposed
__device__ __align__(256) __half g_hidTL[BSZ*HID*SEQ];   // hidden lo, transposed
__device__ __align__(256) __half g_qH   [NS*H*HID];      // queries hi
__device__ __align__(256) __half g_cTH  [NS*H*HID];      // combiners^T hi
__device__ __align__(256) float  g_Pf   [8*H*H];         // Xh^T Xh (upper 128-tiles)
__device__ __align__(256) float  g_Qf   [8*H*H];         // Xh^T Xl
__device__ __align__(256) __half g_KH   [8*H*H];
__device__ __align__(256) __half g_KL   [8*H*H];
__device__ __align__(256) __half g_tmpH [8*H*HID];
__device__ __align__(256) __half g_tmpL [8*H*HID];
__device__ __align__(256) float  g_Mf   [8*H*H];         // M^T
__device__ __align__(256) __half g_MH   [8*H*H];

// ---------------- helpers ----------------
__device__ __forceinline__ void split2h(float v, __half& h, __half& l) {
    h = __float2half_rn(v);
    l = __float2half_rn(v - __half2float(h));
}
__device__ __forceinline__ uint32_t smem_u32(const void* p) {
    uint32_t a;
    asm("{ .reg .u64 t; cvta.to.shared.u64 t, %1; cvt.u32.u64 %0, t; }" : "=r"(a) : "l"(p));
    return a;
}
__device__ __forceinline__ void cpa(uint32_t dst, const void* src) {
    asm volatile("cp.async.cg.shared.global [%0], [%1], 16;" :: "r"(dst), "l"(src));
}
__device__ __forceinline__ void ldsm4(uint32_t (&r)[4], uint32_t addr) {
    asm volatile("ldmatrix.sync.aligned.m8n8.x4.shared.b16 {%0,%1,%2,%3}, [%4];"
        : "=r"(r[0]), "=r"(r[1]), "=r"(r[2]), "=r"(r[3]) : "r"(addr));
}
__device__ __forceinline__ void mma16816(float (&d)[4], const uint32_t (&a)[4],
                                         uint32_t b0, uint32_t b1) {
    asm volatile("mma.sync.aligned.m16n8k16.row.col.f32.f16.f16.f32 "
        "{%0,%1,%2,%3}, {%4,%5,%6,%7}, {%8,%9}, {%0,%1,%2,%3};"
        : "+f"(d[0]), "+f"(d[1]), "+f"(d[2]), "+f"(d[3])
        : "r"(a[0]), "r"(a[1]), "r"(a[2]), "r"(a[3]), "r"(b0), "r"(b1));
}
__device__ __forceinline__ uint32_t swz(int row, int c) {
    return (uint32_t)(row * 64 + ((c ^ ((row >> 1) & 3)) << 4));
}

// Stage layout: Ah[128x32] @0 (8KB), Bh[NTILE x 32] @8K, Bl after (if BPROD==2)
template<int BPROD, int NTILE> struct Lay {
    static constexpr uint32_t BH = 8192u;
    static constexpr uint32_t BN = (NTILE == 128) ? 8192u : 4096u;
    static constexpr uint32_t BL = BH + BN;
    static constexpr uint32_t STAGE = BH + BN * BPROD;
};

template<int BPROD, int NTILE>
__device__ __forceinline__ void load_stage(uint32_t sb,
        const __half* __restrict__ Ah, int lda,
        const __half* __restrict__ Bh, const __half* __restrict__ Bl,
        int ldb, int k0) {
    using L = Lay<BPROD, NTILE>;
    int tid = threadIdx.x;
    #pragma unroll
    for (int t = 0; t < 2; ++t) {
        int cid = tid + t * 256;
        int row = cid >> 2, c = cid & 3;
        uint32_t so = swz(row, c);
        cpa(sb + so, Ah + (size_t)row * lda + k0 + c * 8);
    }
    if (NTILE == 128) {
        #pragma unroll
        for (int t = 0; t < 2; ++t) {
            int cid = tid + t * 256;
            int row = cid >> 2, c = cid & 3;
            uint32_t so = swz(row, c);
            size_t ob = (size_t)row * ldb + k0 + c * 8;
            cpa(sb + L::BH + so, Bh + ob);
            if (BPROD == 2) cpa(sb + L::BL + so, Bl + ob);
        }
    } else {
        int row = tid >> 2, c = tid & 3;
        uint32_t so = swz(row, c);
        size_t ob = (size_t)row * ldb + k0 + c * 8;
        cpa(sb + L::BH + so, Bh + ob);
        if (BPROD == 2) cpa(sb + L::BL + so, Bl + ob);
    }
    asm volatile("cp.async.commit_group;" ::: "memory");
}

// C[128,NTILE] = Ah[128,K] * (Bh (+ Bl))[NTILE,K]^T   (fp16, fp32 accum)
// EPI: 0 = atomicAdd fp32, 1 = store fp32, 2 = split-store fp16 H/L
template<int EPI, int BPROD, int NTILE>
__device__ void gemm_mma(const __half* Ah, int lda,
                         const __half* Bh, const __half* Bl, int ldb, int kIters,
                         float* Cf, __half* CH, __half* CL, int ldc) {
    using L = Lay<BPROD, NTILE>;
    constexpr int MI = (NTILE == 128) ? 4 : 2;
    extern __shared__ char smem[];
    const uint32_t sbase = smem_u32(smem);
    const int tid = threadIdx.x, lane = tid & 31, wid = tid >> 5;
    const int wm = (NTILE == 128) ? (wid & 1) : (wid & 3);
    const int wn = (NTILE == 128) ? (wid >> 1) : (wid >> 2);

    float acc[MI][4][4];
    #pragma unroll
    for (int i = 0; i < MI; ++i)
        #pragma unroll
        for (int j = 0; j < 4; ++j)
            #pragma unroll
            for (int v = 0; v < 4; ++v) acc[i][j][v] = 0.f;

    load_stage<BPROD, NTILE>(sbase,            Ah, lda, Bh, Bl, ldb, 0);
    load_stage<BPROD, NTILE>(sbase + L::STAGE, Ah, lda, Bh, Bl, ldb, 32);

    const int mi = lane >> 3, lr = lane & 7;
    const int rA0 = wm * (MI * 16) + (mi & 1) * 8 + lr;
    const int rB0 = wn * 32 + (mi & 1) * 8 + lr;
    const int chb = mi >> 1;

    for (int it = 0; it < kIters; ++it) {
        if (it + 1 < kIters)
            asm volatile("cp.async.wait_group 1;" ::: "memory");
        else
            asm volatile("cp.async.wait_group 0;" ::: "memory");
        __syncthreads();

        uint32_t sb = sbase + (uint32_t)(it % 3) * L::STAGE;
        if (it + 2 < kIters)
            load_stage<BPROD, NTILE>(sbase + (uint32_t)((it + 2) % 3) * L::STAGE,
                                     Ah, lda, Bh, Bl, ldb, (it + 2) * 32);

        #pragma unroll
        for (int kk = 0; kk < 2; ++kk) {
            int c = kk * 2 + chb;
            uint32_t a[MI][4], bh[2][4], bl[2][4];
            #pragma unroll
            for (int j = 0; j < 2; ++j) {
                int r = rB0 + j * 16;
                uint32_t so = swz(r, c);
                ldsm4(bh[j], sb + L::BH + so);
                if (BPROD == 2) ldsm4(bl[j], sb + L::BL + so);
            }
            #pragma unroll
            for (int i = 0; i < MI; ++i) {
                int r = rA0 + i * 16;
                ldsm4(a[i], sb + swz(r, c));
            }
            #pragma unroll
            for (int i = 0; i < MI; ++i)
                #pragma unroll
                for (int j = 0; j < 4; ++j) {
                    int j2 = j >> 1, jo = j & 1;
                    mma16816(acc[i][j], a[i], bh[j2][jo], bh[j2][jo + 2]);
                    if (BPROD == 2)
                        mma16816(acc[i][j], a[i], bl[j2][jo], bl[j2][jo + 2]);
                }
        }
    }

    #pragma unroll
    for (int i = 0; i < MI; ++i)
        #pragma unroll
        for (int j = 0; j < 4; ++j) {
            int r   = wm * (MI * 16) + i * 16 + (lane >> 2);
            int col = wn * 32 + j * 8 + (lane & 3) * 2;
            if (EPI == 0) {
                atomicAdd(Cf + (size_t)r * ldc + col,           acc[i][j][0]);
                atomicAdd(Cf + (size_t)r * ldc + col + 1,       acc[i][j][1]);
                atomicAdd(Cf + (size_t)(r + 8) * ldc + col,     acc[i][j][2]);
                atomicAdd(Cf + (size_t)(r + 8) * ldc + col + 1, acc[i][j][3]);
            } else if (EPI == 1) {
                *reinterpret_cast<float2*>(Cf + (size_t)r * ldc + col) =
                    make_float2(acc[i][j][0], acc[i][j][1]);
                *reinterpret_cast<float2*>(Cf + (size_t)(r + 8) * ldc + col) =
                    make_float2(acc[i][j][2], acc[i][j][3]);
            } else {
                __half h0, l0, h1, l1;
                __half2 ph, pl;
                split2h(acc[i][j][0], h0, l0); split2h(acc[i][j][1], h1, l1);
                ph.x = h0; ph.y = h1; pl.x = l0; pl.y = l1;
                *reinterpret_cast<__half2*>(CH + (size_t)r * ldc + col) = ph;
                *reinterpret_cast<__half2*>(CL + (size_t)r * ldc + col) = pl;
                split2h(acc[i][j][2], h0, l0); split2h(acc[i][j][3], h1, l1);
                ph.x = h0; ph.y = h1; pl.x = l0; pl.y = l1;
                *reinterpret_cast<__half2*>(CH + (size_t)(r + 8) * ldc + col) = ph;
                *reinterpret_cast<__half2*>(CL + (size_t)(r + 8) * ldc + col) = pl;
            }
        }
}

// ---- pass wrappers ----
// P = Xh^T Xh (sel 0, upper tiles only), Q = Xh^T Xl (sel 1); split-K x4 over t
__global__ void __launch_bounds__(256, 2) k_p1() {
    int z = blockIdx.z;
    int sel = z >> 5, w = z & 31, pair = w >> 2, split = w & 3;
    int b = pair >> 2, q = pair & 3;
    int m0 = blockIdx.x * 128, n0 = blockIdx.y * 128;
    if (sel == 0 && m0 > n0) return;       // P symmetric: skip lower tile
    size_t base = ((size_t)b * HID + q * H) * SEQ + split * 512;
    const __half* A  = g_hidTH + base + (size_t)m0 * SEQ;
    const __half* Bh = (sel ? g_hidTL : g_hidTH) + base + (size_t)n0 * SEQ;
    float* dst = (sel ? g_Qf : g_Pf) + (size_t)pair * H * H + m0 * H + n0;
    gemm_mma<0, 1, 128>(A, SEQ, Bh, nullptr, SEQ, 16, dst, nullptr, nullptr, H);
}
// K = P + Q + Q^T (P mirrored where only upper tile stored), split to fp16 KH/KL
__global__ void __launch_bounds__(256) k_combK() {
    __shared__ float shQ[32][33], shP[32][33];
    int pair = blockIdx.z, it = blockIdx.y, jt = blockIdx.x;
    int tx = threadIdx.x & 31, ty = threadIdx.x >> 5;
    const float* P = g_Pf + (size_t)pair * H * H;
    const float* Q = g_Qf + (size_t)pair * H * H;
    bool mirror = (it >> 2) > (jt >> 2);   // P 128-tile (1,0) not stored -> use (0,1)^T
    #pragma unroll
    for (int i = 0; i < 4; ++i) {
        int r = ty + i * 8;
        shQ[r][tx] = Q[(size_t)(jt * 32 + r) * H + it * 32 + tx];
        if (mirror)
            shP[r][tx] = P[(size_t)(jt * 32 + r) * H + it * 32 + tx];
    }
    __syncthreads();
    #pragma unroll
    for (int i = 0; i < 4; ++i) {
        int r = ty + i * 8;
        int row = it * 32 + r, col = jt * 32 + tx;
        size_t idx = (size_t)pair * H * H + (size_t)row * H + col;
        float pv = mirror ? shP[tx][r] : P[(size_t)row * H + col];
        float v = pv + Q[(size_t)row * H + col] + shQ[tx][r];
        __half h, l; split2h(v, h, l);
        g_KH[idx] = h; g_KL[idx] = l;
    }
}
// p2: tmp = qw_h * (Kh + Kl)  (K symmetric), direct split-store
__global__ void __launch_bounds__(256, 2) k_p2() {
    int z = blockIdx.z, b = z >> 4, a = (z >> 2) & 3, q = z & 3;
    int m0 = blockIdx.x * 128, n0 = blockIdx.y * 64;
    size_t ab = (size_t)a * H * HID + (size_t)m0 * HID + q * H;
    size_t bb = (size_t)((b << 2) | q) * H * H + (size_t)n0 * H;
    size_t cb = (size_t)((b << 2) | a) * H * HID + (size_t)m0 * HID + q * H + n0;
    gemm_mma<2, 2, 64>(g_qH + ab, HID, g_KH + bb, g_KL + bb, H,
                       8, nullptr, g_tmpH + cb, g_tmpL + cb, HID);
}
// p3: M^T = cT_h * (tmpH + tmpL)^T, split-K x4
__global__ void __launch_bounds__(256, 2) k_p3() {
    int z = blockIdx.z, pair = z >> 2, split = z & 3;
    int a = pair & 3;
    int m0 = blockIdx.x * 128, n0 = blockIdx.y * 64;
    size_t ab = (size_t)a * H * HID + (size_t)m0 * HID + split * 256;
    size_t bb = (size_t)pair * H * HID + (size_t)n0 * HID + split * 256;
    gemm_mma<0, 2, 64>(g_cTH + ab, HID, g_tmpH + bb, g_tmpL + bb, HID,
                       8, g_Mf + (size_t)pair * H * H + m0 * H + n0, nullptr, nullptr, H);
}
// convert M^T -> MH fp16 (single product in p4)
__global__ void __launch_bounds__(256) k_cvtM() {
    size_t i = (size_t)blockIdx.x * 2048 + threadIdx.x * 8;
    #pragma unroll
    for (int j = 0; j < 8; ++j)
        g_MH[i + j] = __float2half_rn(g_Mf[i + j]);
}
// p4: out = hid_h * Mh (single product)
__global__ void __launch_bounds__(256, 2) k_p4(float* __restrict__ out) {
    int pair = blockIdx.z, b = pair >> 2, a = pair & 3;
    int m0 = blockIdx.x * 128, n0 = blockIdx.y * 128;
    size_t ab = (size_t)b * SEQ * HID + (size_t)m0 * HID + a * H;
    size_t bb = (size_t)pair * H * H + (size_t)n0 * H;
    gemm_mma<1, 1, 128>(g_hidH + ab, HID, g_MH + bb, nullptr, H,
                        8, out + ab + n0, nullptr, nullptr, HID);
}

// ---- merged prep ----
// blocks [0,1024): hidden 64x64 split+transpose; [1024,2048): queries;
// [2048,3072): combiners T; [3072,3456): zero Pf/Qf/Mf
__global__ void __launch_bounds__(256) k_prep(const float* __restrict__ hid,
                                              const float* __restrict__ q,
                                              const float* __restrict__ c) {
    int blk = blockIdx.x, tid = threadIdx.x;
    if (blk < 1024) {
        __shared__ __half shH[64][65], shL[64][65];
        int b = blk >> 9, tt = (blk >> 4) & 31, ft = blk & 15;
        int w = tid >> 5, l = tid & 31;
        int t0 = tt * 64, f0 = ft * 64;
        #pragma unroll
        for (int i = 0; i < 8; ++i) {
            int r = w * 8 + i;              // t-row within tile
            size_t gi = ((size_t)b * SEQ + t0 + r) * HID + f0 + l * 2;
            float2 v = *reinterpret_cast<const float2*>(hid + gi);
            __half h0, l0, h1, l1;
            split2h(v.x, h0, l0); split2h(v.y, h1, l1);
            shH[r][l * 2] = h0; shH[r][l * 2 + 1] = h1;
            shL[r][l * 2] = l0; shL[r][l * 2 + 1] = l1;
            __half2 ph; ph.x = h0; ph.y = h1;
            *reinterpret_cast<__half2*>(g_hidH + gi) = ph;
        }
        __syncthreads();
        #pragma unroll
        for (int i = 0; i < 8; ++i) {
            int fr = w * 8 + i;             // f-row within tile
            size_t gi = ((size_t)b * HID + f0 + fr) * SEQ + t0 + l * 2;
            __half2 hv, lv;
            hv.x = shH[l * 2][fr]; hv.y = shH[l * 2 + 1][fr];
            lv.x = shL[l * 2][fr]; lv.y = shL[l * 2 + 1][fr];
            *reinterpret_cast<__half2*>(g_hidTH + gi) = hv;
            *reinterpret_cast<__half2*>(g_hidTL + gi) = lv;
        }
    } else if (blk < 2048) {
        size_t i = (size_t)(blk - 1024) * 1024 + tid * 4;
        float4 v = *reinterpret_cast<const float4*>(q + i);
        __half2 p0, p1;
        p0.x = __float2half_rn(v.x); p0.y = __float2half_rn(v.y);
        p1.x = __float2half_rn(v.z); p1.y = __float2half_rn(v.w);
        *reinterpret_cast<__half2*>(g_qH + i)     = p0;
        *reinterpret_cast<__half2*>(g_qH + i + 2) = p1;
    } else if (blk < 3072) {
        __shared__ __half sh[32][33];
        int z = blk - 2048;
        int a = z >> 8, kt = (z >> 3) & 31, gt = z & 7;
        int tx = tid & 31, ty = tid >> 5;
        int k0 = kt * 32, g0 = gt * 32;
        #pragma unroll
        for (int i = 0; i < 4; ++i) {
            int r = ty + i * 8;
            sh[r][tx] = __float2half_rn(c[((size_t)a * HID + k0 + r) * H + g0 + tx]);
        }
        __syncthreads();
        #pragma unroll
        for (int i = 0; i < 4; ++i) {
            int r = ty + i * 8;
            g_cTH[((size_t)a * H + g0 + r) * HID + k0 + tx] = sh[tx][r];
        }
    } else {
        int z = blk - 3072;                 // 0..383 : zero Pf, Qf, Mf
        float* dst = (z < 128) ? g_Pf : ((z < 256) ? g_Qf : g_Mf);
        size_t base = (size_t)(z & 127) * 4096 + tid * 16;
        float4 zv = make_float4(0.f, 0.f, 0.f, 0.f);
        #pragma unroll
        for (int i = 0; i < 4; ++i)
            *reinterpret_cast<float4*>(dst + base + i * 4) = zv;
    }
}

extern "C" void kernel_launch(void* const* d_in, const int* in_sizes, int n_in,
                              void* d_out, int out_size) {
    const float* hidden    = (const float*)d_in[0];
    const float* queries   = (const float*)d_in[1];
    const float* combiners = (const float*)d_in[2];
    float* out = (float*)d_out;

    cudaFuncSetAttribute(k_p1, cudaFuncAttributeMaxDynamicSharedMemorySize, 49152);
    cudaFuncSetAttribute(k_p2, cudaFuncAttributeMaxDynamicSharedMemorySize, 49152);
    cudaFuncSetAttribute(k_p3, cudaFuncAttributeMaxDynamicSharedMemorySize, 49152);
    cudaFuncSetAttribute(k_p4, cudaFuncAttributeMaxDynamicSharedMemorySize, 49152);

    k_prep<<<3456, 256>>>(hidden, queries, combiners);
    k_p1<<<dim3(2, 2, 64), 256, 49152>>>();
    k_combK<<<dim3(8, 8, 8), 256>>>();
    k_p2<<<dim3(2, 4, 32), 256, 49152>>>();
    k_p3<<<dim3(2, 4, 32), 256, 49152>>>();
    k_cvtM<<<256, 256>>>();
    k_p4<<<dim3(16, 2, 8), 256, 49152>>>(out);
}

// round 10
// speedup vs baseline: 1.7193x; 1.0989x over previous
#include <cuda_runtime.h>
#include <cuda_fp16.h>
#include <cstdint>

#define BSZ 2
#define SEQ 2048
#define HID 1024
#define NS  4
#define H   256

// ---------------- device scratch ----------------
__device__ __align__(256) __half g_hidH [BSZ*SEQ*HID];   // hidden hi, row-major
__device__ __align__(256) __half g_hidTH[BSZ*HID*SEQ];   // hidden hi, transposed
__device__ __align__(256) __half g_hidTL[BSZ*HID*SEQ];   // hidden lo, transposed
__device__ __align__(256) __half g_qH   [NS*H*HID];      // queries hi
__device__ __align__(256) __half g_cTH  [NS*H*HID];      // combiners^T hi
__device__ __align__(256) float  g_Pf   [8*H*H];         // Xh^T Xh (upper 128-tiles)
__device__ __align__(256) float  g_Qf   [8*H*H];         // Xh^T Xl
__device__ __align__(256) __half g_KH   [8*H*H];
__device__ __align__(256) __half g_tmpH [8*H*HID];
__device__ __align__(256) float  g_Mf   [8*H*H];         // M^T
__device__ __align__(256) __half g_MH   [8*H*H];

// ---------------- helpers ----------------
__device__ __forceinline__ void split2h(float v, __half& h, __half& l) {
    h = __float2half_rn(v);
    l = __float2half_rn(v - __half2float(h));
}
__device__ __forceinline__ uint32_t smem_u32(const void* p) {
    uint32_t a;
    asm("{ .reg .u64 t; cvta.to.shared.u64 t, %1; cvt.u32.u64 %0, t; }" : "=r"(a) : "l"(p));
    return a;
}
__device__ __forceinline__ void cpa(uint32_t dst, const void* src) {
    asm volatile("cp.async.cg.shared.global [%0], [%1], 16;" :: "r"(dst), "l"(src));
}
__device__ __forceinline__ void ldsm4(uint32_t (&r)[4], uint32_t addr) {
    asm volatile("ldmatrix.sync.aligned.m8n8.x4.shared.b16 {%0,%1,%2,%3}, [%4];"
        : "=r"(r[0]), "=r"(r[1]), "=r"(r[2]), "=r"(r[3]) : "r"(addr));
}
__device__ __forceinline__ void mma16816(float (&d)[4], const uint32_t (&a)[4],
                                         uint32_t b0, uint32_t b1) {
    asm volatile("mma.sync.aligned.m16n8k16.row.col.f32.f16.f16.f32 "
        "{%0,%1,%2,%3}, {%4,%5,%6,%7}, {%8,%9}, {%0,%1,%2,%3};"
        : "+f"(d[0]), "+f"(d[1]), "+f"(d[2]), "+f"(d[3])
        : "r"(a[0]), "r"(a[1]), "r"(a[2]), "r"(a[3]), "r"(b0), "r"(b1));
}
__device__ __forceinline__ uint32_t swz(int row, int c) {
    return (uint32_t)(row * 64 + ((c ^ ((row >> 1) & 3)) << 4));
}

// Stage layout: Ah[128x32] @0 (8KB), Bh[NTILE x 32] @8K, Bl after (if BPROD==2)
template<int BPROD, int NTILE> struct Lay {
    static constexpr uint32_t BH = 8192u;
    static constexpr uint32_t BN = (NTILE == 128) ? 8192u : 4096u;
    static constexpr uint32_t BL = BH + BN;
    static constexpr uint32_t STAGE = BH + BN * BPROD;
};

template<int BPROD, int NTILE>
__device__ __forceinline__ void load_stage(uint32_t sb,
        const __half* __restrict__ Ah, int lda,
        const __half* __restrict__ Bh, const __half* __restrict__ Bl,
        int ldb, int k0) {
    using L = Lay<BPROD, NTILE>;
    int tid = threadIdx.x;
    #pragma unroll
    for (int t = 0; t < 2; ++t) {
        int cid = tid + t * 256;
        int row = cid >> 2, c = cid & 3;
        uint32_t so = swz(row, c);
        cpa(sb + so, Ah + (size_t)row * lda + k0 + c * 8);
    }
    if (NTILE == 128) {
        #pragma unroll
        for (int t = 0; t < 2; ++t) {
            int cid = tid + t * 256;
            int row = cid >> 2, c = cid & 3;
            uint32_t so = swz(row, c);
            size_t ob = (size_t)row * ldb + k0 + c * 8;
            cpa(sb + L::BH + so, Bh + ob);
            if (BPROD == 2) cpa(sb + L::BL + so, Bl + ob);
        }
    } else {
        int row = tid >> 2, c = tid & 3;
        uint32_t so = swz(row, c);
        size_t ob = (size_t)row * ldb + k0 + c * 8;
        cpa(sb + L::BH + so, Bh + ob);
        if (BPROD == 2) cpa(sb + L::BL + so, Bl + ob);
    }
    asm volatile("cp.async.commit_group;" ::: "memory");
}

// C[128,NTILE] = Ah[128,K] * (Bh (+ Bl))[NTILE,K]^T   (fp16, fp32 accum)
// EPI: 0 = atomicAdd fp32, 1 = store fp32, 2 = store fp16
template<int EPI, int BPROD, int NTILE>
__device__ void gemm_mma(const __half* Ah, int lda,
                         const __half* Bh, const __half* Bl, int ldb, int kIters,
                         float* Cf, __half* CH, int ldc) {
    using L = Lay<BPROD, NTILE>;
    constexpr int MI = (NTILE == 128) ? 4 : 2;
    extern __shared__ char smem[];
    const uint32_t sbase = smem_u32(smem);
    const int tid = threadIdx.x, lane = tid & 31, wid = tid >> 5;
    const int wm = (NTILE == 128) ? (wid & 1) : (wid & 3);
    const int wn = (NTILE == 128) ? (wid >> 1) : (wid >> 2);

    float acc[MI][4][4];
    #pragma unroll
    for (int i = 0; i < MI; ++i)
        #pragma unroll
        for (int j = 0; j < 4; ++j)
            #pragma unroll
            for (int v = 0; v < 4; ++v) acc[i][j][v] = 0.f;

    load_stage<BPROD, NTILE>(sbase,            Ah, lda, Bh, Bl, ldb, 0);
    load_stage<BPROD, NTILE>(sbase + L::STAGE, Ah, lda, Bh, Bl, ldb, 32);

    const int mi = lane >> 3, lr = lane & 7;
    const int rA0 = wm * (MI * 16) + (mi & 1) * 8 + lr;
    const int rB0 = wn * 32 + (mi & 1) * 8 + lr;
    const int chb = mi >> 1;

    for (int it = 0; it < kIters; ++it) {
        if (it + 1 < kIters)
            asm volatile("cp.async.wait_group 1;" ::: "memory");
        else
            asm volatile("cp.async.wait_group 0;" ::: "memory");
        __syncthreads();

        uint32_t sb = sbase + (uint32_t)(it % 3) * L::STAGE;
        if (it + 2 < kIters)
            load_stage<BPROD, NTILE>(sbase + (uint32_t)((it + 2) % 3) * L::STAGE,
                                     Ah, lda, Bh, Bl, ldb, (it + 2) * 32);

        #pragma unroll
        for (int kk = 0; kk < 2; ++kk) {
            int c = kk * 2 + chb;
            uint32_t a[MI][4], bh[2][4], bl[2][4];
            #pragma unroll
            for (int j = 0; j < 2; ++j) {
                int r = rB0 + j * 16;
                uint32_t so = swz(r, c);
                ldsm4(bh[j], sb + L::BH + so);
                if (BPROD == 2) ldsm4(bl[j], sb + L::BL + so);
            }
            #pragma unroll
            for (int i = 0; i < MI; ++i) {
                int r = rA0 + i * 16;
                ldsm4(a[i], sb + swz(r, c));
            }
            #pragma unroll
            for (int i = 0; i < MI; ++i)
                #pragma unroll
                for (int j = 0; j < 4; ++j) {
                    int j2 = j >> 1, jo = j & 1;
                    mma16816(acc[i][j], a[i], bh[j2][jo], bh[j2][jo + 2]);
                    if (BPROD == 2)
                        mma16816(acc[i][j], a[i], bl[j2][jo], bl[j2][jo + 2]);
                }
        }
    }

    #pragma unroll
    for (int i = 0; i < MI; ++i)
        #pragma unroll
        for (int j = 0; j < 4; ++j) {
            int r   = wm * (MI * 16) + i * 16 + (lane >> 2);
            int col = wn * 32 + j * 8 + (lane & 3) * 2;
            if (EPI == 0) {
                atomicAdd(Cf + (size_t)r * ldc + col,           acc[i][j][0]);
                atomicAdd(Cf + (size_t)r * ldc + col + 1,       acc[i][j][1]);
                atomicAdd(Cf + (size_t)(r + 8) * ldc + col,     acc[i][j][2]);
                atomicAdd(Cf + (size_t)(r + 8) * ldc + col + 1, acc[i][j][3]);
            } else if (EPI == 1) {
                *reinterpret_cast<float2*>(Cf + (size_t)r * ldc + col) =
                    make_float2(acc[i][j][0], acc[i][j][1]);
                *reinterpret_cast<float2*>(Cf + (size_t)(r + 8) * ldc + col) =
                    make_float2(acc[i][j][2], acc[i][j][3]);
            } else {
                __half2 p0, p1;
                p0.x = __float2half_rn(acc[i][j][0]);
                p0.y = __float2half_rn(acc[i][j][1]);
                p1.x = __float2half_rn(acc[i][j][2]);
                p1.y = __float2half_rn(acc[i][j][3]);
                *reinterpret_cast<__half2*>(CH + (size_t)r * ldc + col)       = p0;
                *reinterpret_cast<__half2*>(CH + (size_t)(r + 8) * ldc + col) = p1;
            }
        }
}

// ---- pass wrappers ----
// P = Xh^T Xh (sel 0, upper tiles only), Q = Xh^T Xl (sel 1); split-K x4 over t
__global__ void __launch_bounds__(256, 2) k_p1() {
    int z = blockIdx.z;
    int sel = z >> 5, w = z & 31, pair = w >> 2, split = w & 3;
    int b = pair >> 2, q = pair & 3;
    int m0 = blockIdx.x * 128, n0 = blockIdx.y * 128;
    if (sel == 0 && m0 > n0) return;       // P symmetric: skip lower tile
    size_t base = ((size_t)b * HID + q * H) * SEQ + split * 512;
    const __half* A  = g_hidTH + base + (size_t)m0 * SEQ;
    const __half* Bh = (sel ? g_hidTL : g_hidTH) + base + (size_t)n0 * SEQ;
    float* dst = (sel ? g_Qf : g_Pf) + (size_t)pair * H * H + m0 * H + n0;
    gemm_mma<0, 1, 128>(A, SEQ, Bh, nullptr, SEQ, 16, dst, nullptr, H);
}
// K = P + Q + Q^T (P mirrored where only upper tile stored) -> fp16 KH
__global__ void __launch_bounds__(256) k_combK() {
    __shared__ float shQ[32][33], shP[32][33];
    int pair = blockIdx.z, it = blockIdx.y, jt = blockIdx.x;
    int tx = threadIdx.x & 31, ty = threadIdx.x >> 5;
    const float* P = g_Pf + (size_t)pair * H * H;
    const float* Q = g_Qf + (size_t)pair * H * H;
    bool mirror = (it >> 2) > (jt >> 2);   // P 128-tile (1,0) not stored -> use (0,1)^T
    #pragma unroll
    for (int i = 0; i < 4; ++i) {
        int r = ty + i * 8;
        shQ[r][tx] = Q[(size_t)(jt * 32 + r) * H + it * 32 + tx];
        if (mirror)
            shP[r][tx] = P[(size_t)(jt * 32 + r) * H + it * 32 + tx];
    }
    __syncthreads();
    #pragma unroll
    for (int i = 0; i < 4; ++i) {
        int r = ty + i * 8;
        int row = it * 32 + r, col = jt * 32 + tx;
        size_t idx = (size_t)pair * H * H + (size_t)row * H + col;
        float pv = mirror ? shP[tx][r] : P[(size_t)row * H + col];
        g_KH[idx] = __float2half_rn(pv + Q[(size_t)row * H + col] + shQ[tx][r]);
    }
}
// p2: tmp = qw_h * Kh  (K symmetric), fp16 store, single product
__global__ void __launch_bounds__(256, 2) k_p2() {
    int z = blockIdx.z, b = z >> 4, a = (z >> 2) & 3, q = z & 3;
    int m0 = blockIdx.x * 128, n0 = blockIdx.y * 64;
    size_t ab = (size_t)a * H * HID + (size_t)m0 * HID + q * H;
    size_t bb = (size_t)((b << 2) | q) * H * H + (size_t)n0 * H;
    size_t cb = (size_t)((b << 2) | a) * H * HID + (size_t)m0 * HID + q * H + n0;
    gemm_mma<2, 1, 64>(g_qH + ab, HID, g_KH + bb, nullptr, H,
                       8, nullptr, g_tmpH + cb, HID);
}
// p3: M^T = cT_h * tmpH^T, split-K x4, single product
__global__ void __launch_bounds__(256, 2) k_p3() {
    int z = blockIdx.z, pair = z >> 2, split = z & 3;
    int a = pair & 3;
    int m0 = blockIdx.x * 128, n0 = blockIdx.y * 64;
    size_t ab = (size_t)a * H * HID + (size_t)m0 * HID + split * 256;
    size_t bb = (size_t)pair * H * HID + (size_t)n0 * HID + split * 256;
    gemm_mma<0, 1, 64>(g_cTH + ab, HID, g_tmpH + bb, nullptr, HID,
                       8, g_Mf + (size_t)pair * H * H + m0 * H + n0, nullptr, H);
}
// convert M^T -> MH fp16
__global__ void __launch_bounds__(256) k_cvtM() {
    size_t i = (size_t)blockIdx.x * 2048 + threadIdx.x * 8;
    #pragma unroll
    for (int j = 0; j < 8; ++j)
        g_MH[i + j] = __float2half_rn(g_Mf[i + j]);
}
// p4: out = hid_h * Mh (single product)
__global__ void __launch_bounds__(256, 2) k_p4(float* __restrict__ out) {
    int pair = blockIdx.z, b = pair >> 2, a = pair & 3;
    int m0 = blockIdx.x * 128, n0 = blockIdx.y * 128;
    size_t ab = (size_t)b * SEQ * HID + (size_t)m0 * HID + a * H;
    size_t bb = (size_t)pair * H * H + (size_t)n0 * H;
    gemm_mma<1, 1, 128>(g_hidH + ab, HID, g_MH + bb, nullptr, H,
                        8, out + ab + n0, nullptr, HID);
}

// ---- merged prep ----
__global__ void __launch_bounds__(256) k_prep(const float* __restrict__ hid,
                                              const float* __restrict__ q,
                                              const float* __restrict__ c) {
    int blk = blockIdx.x, tid = threadIdx.x;
    if (blk < 1024) {
        __shared__ __half shH[64][65], shL[64][65];
        int b = blk >> 9, tt = (blk >> 4) & 31, ft = blk & 15;
        int w = tid >> 5, l = tid & 31;
        int t0 = tt * 64, f0 = ft * 64;
        #pragma unroll
        for (int i = 0; i < 8; ++i) {
            int r = w * 8 + i;
            size_t gi = ((size_t)b * SEQ + t0 + r) * HID + f0 + l * 2;
            float2 v = *reinterpret_cast<const float2*>(hid + gi);
            __half h0, l0, h1, l1;
            split2h(v.x, h0, l0); split2h(v.y, h1, l1);
            shH[r][l * 2] = h0; shH[r][l * 2 + 1] = h1;
            shL[r][l * 2] = l0; shL[r][l * 2 + 1] = l1;
            __half2 ph; ph.x = h0; ph.y = h1;
            *reinterpret_cast<__half2*>(g_hidH + gi) = ph;
        }
        __syncthreads();
        #pragma unroll
        for (int i = 0; i < 8; ++i) {
            int fr = w * 8 + i;
            size_t gi = ((size_t)b * HID + f0 + fr) * SEQ + t0 + l * 2;
            __half2 hv, lv;
            hv.x = shH[l * 2][fr]; hv.y = shH[l * 2 + 1][fr];
            lv.x = shL[l * 2][fr]; lv.y = shL[l * 2 + 1][fr];
            *reinterpret_cast<__half2*>(g_hidTH + gi) = hv;
            *reinterpret_cast<__half2*>(g_hidTL + gi) = lv;
        }
    } else if (blk < 2048) {
        size_t i = (size_t)(blk - 1024) * 1024 + tid * 4;
        float4 v = *reinterpret_cast<const float4*>(q + i);
        __half2 p0, p1;
        p0.x = __float2half_rn(v.x); p0.y = __float2half_rn(v.y);
        p1.x = __float2half_rn(v.z); p1.y = __float2half_rn(v.w);
        *reinterpret_cast<__half2*>(g_qH + i)     = p0;
        *reinterpret_cast<__half2*>(g_qH + i + 2) = p1;
    } else if (blk < 3072) {
        __shared__ __half sh[32][33];
        int z = blk - 2048;
        int a = z >> 8, kt = (z >> 3) & 31, gt = z & 7;
        int tx = tid & 31, ty = tid >> 5;
        int k0 = kt * 32, g0 = gt * 32;
        #pragma unroll
        for (int i = 0; i < 4; ++i) {
            int r = ty + i * 8;
            sh[r][tx] = __float2half_rn(c[((size_t)a * HID + k0 + r) * H + g0 + tx]);
        }
        __syncthreads();
        #pragma unroll
        for (int i = 0; i < 4; ++i) {
            int r = ty + i * 8;
            g_cTH[((size_t)a * H + g0 + r) * HID + k0 + tx] = sh[tx][r];
        }
    } else {
        int z = blk - 3072;                 // 0..383 : zero Pf, Qf, Mf
        float* dst = (z < 128) ? g_Pf : ((z < 256) ? g_Qf : g_Mf);
        size_t base = (size_t)(z & 127) * 4096 + tid * 16;
        float4 zv = make_float4(0.f, 0.f, 0.f, 0.f);
        #pragma unroll
        for (int i = 0; i < 4; ++i)
            *reinterpret_cast<float4*>(dst + base + i * 4) = zv;
    }
}

extern "C" void kernel_launch(void* const* d_in, const int* in_sizes, int n_in,
                              void* d_out, int out_size) {
    const float* hidden    = (const float*)d_in[0];
    const float* queries   = (const float*)d_in[1];
    const float* combiners = (const float*)d_in[2];
    float* out = (float*)d_out;

    cudaFuncSetAttribute(k_p1, cudaFuncAttributeMaxDynamicSharedMemorySize, 49152);
    cudaFuncSetAttribute(k_p2, cudaFuncAttributeMaxDynamicSharedMemorySize, 36864);
    cudaFuncSetAttribute(k_p3, cudaFuncAttributeMaxDynamicSharedMemorySize, 36864);
    cudaFuncSetAttribute(k_p4, cudaFuncAttributeMaxDynamicSharedMemorySize, 49152);

    k_prep<<<3456, 256>>>(hidden, queries, combiners);
    k_p1<<<dim3(2, 2, 64), 256, 49152>>>();
    k_combK<<<dim3(8, 8, 8), 256>>>();
    k_p2<<<dim3(2, 4, 32), 256, 36864>>>();
    k_p3<<<dim3(2, 4, 32), 256, 36864>>>();
    k_cvtM<<<256, 256>>>();
    k_p4<<<dim3(16, 2, 8), 256, 49152>>>(out);
}

// round 11
// speedup vs baseline: 1.9797x; 1.1515x over previous
#include <cuda_runtime.h>
#include <cuda_fp16.h>
#include <cstdint>

#define BSZ 2
#define SEQ 2048
#define HID 1024
#define NS  4
#define H   256

// ---------------- device scratch ----------------
__device__ __align__(256) __half g_hidH [BSZ*SEQ*HID];   // hidden hi, row-major
__device__ __align__(256) __half g_hidTH[BSZ*HID*SEQ];   // hidden hi, transposed
__device__ __align__(256) __half g_qH   [NS*H*HID];      // queries hi
__device__ __align__(256) __half g_cTH  [NS*H*HID];      // combiners^T hi
__device__ __align__(256) float  g_Pf   [8*H*H];         // Xh^T Xh (upper 128-tiles)
__device__ __align__(256) __half g_KH   [8*H*H];
__device__ __align__(256) __half g_tmpH [8*H*HID];
__device__ __align__(256) float  g_Mf   [8*H*H];         // M^T
__device__ __align__(256) __half g_MH   [8*H*H];

// ---------------- helpers ----------------
__device__ __forceinline__ uint32_t smem_u32(const void* p) {
    uint32_t a;
    asm("{ .reg .u64 t; cvta.to.shared.u64 t, %1; cvt.u32.u64 %0, t; }" : "=r"(a) : "l"(p));
    return a;
}
__device__ __forceinline__ void cpa(uint32_t dst, const void* src) {
    asm volatile("cp.async.cg.shared.global [%0], [%1], 16;" :: "r"(dst), "l"(src));
}
__device__ __forceinline__ void ldsm4(uint32_t (&r)[4], uint32_t addr) {
    asm volatile("ldmatrix.sync.aligned.m8n8.x4.shared.b16 {%0,%1,%2,%3}, [%4];"
        : "=r"(r[0]), "=r"(r[1]), "=r"(r[2]), "=r"(r[3]) : "r"(addr));
}
__device__ __forceinline__ void mma16816(float (&d)[4], const uint32_t (&a)[4],
                                         uint32_t b0, uint32_t b1) {
    asm volatile("mma.sync.aligned.m16n8k16.row.col.f32.f16.f16.f32 "
        "{%0,%1,%2,%3}, {%4,%5,%6,%7}, {%8,%9}, {%0,%1,%2,%3};"
        : "+f"(d[0]), "+f"(d[1]), "+f"(d[2]), "+f"(d[3])
        : "r"(a[0]), "r"(a[1]), "r"(a[2]), "r"(a[3]), "r"(b0), "r"(b1));
}
__device__ __forceinline__ uint32_t swz(int row, int c) {
    return (uint32_t)(row * 64 + ((c ^ ((row >> 1) & 3)) << 4));
}

// Stage layout: Ah[128x32] @0 (8KB), Bh[NTILE x 32] @8K
template<int NTILE> struct Lay {
    static constexpr uint32_t BH = 8192u;
    static constexpr uint32_t BN = (NTILE == 128) ? 8192u : 4096u;
    static constexpr uint32_t STAGE = BH + BN;
};

template<int NTILE>
__device__ __forceinline__ void load_stage(uint32_t sb,
        const __half* __restrict__ Ah, int lda,
        const __half* __restrict__ Bh, int ldb, int k0) {
    using L = Lay<NTILE>;
    int tid = threadIdx.x;
    #pragma unroll
    for (int t = 0; t < 2; ++t) {
        int cid = tid + t * 256;
        int row = cid >> 2, c = cid & 3;
        uint32_t so = swz(row, c);
        cpa(sb + so, Ah + (size_t)row * lda + k0 + c * 8);
    }
    if (NTILE == 128) {
        #pragma unroll
        for (int t = 0; t < 2; ++t) {
            int cid = tid + t * 256;
            int row = cid >> 2, c = cid & 3;
            uint32_t so = swz(row, c);
            cpa(sb + L::BH + so, Bh + (size_t)row * ldb + k0 + c * 8);
        }
    } else {
        int row = tid >> 2, c = tid & 3;
        uint32_t so = swz(row, c);
        cpa(sb + L::BH + so, Bh + (size_t)row * ldb + k0 + c * 8);
    }
    asm volatile("cp.async.commit_group;" ::: "memory");
}

// C[128,NTILE] = Ah[128,K] * Bh[NTILE,K]^T   (fp16, fp32 accum)
// EPI: 0 = atomicAdd fp32, 1 = store fp32, 2 = store fp16
template<int EPI, int NTILE>
__device__ void gemm_mma(const __half* Ah, int lda,
                         const __half* Bh, int ldb, int kIters,
                         float* Cf, __half* CH, int ldc) {
    using L = Lay<NTILE>;
    constexpr int MI = (NTILE == 128) ? 4 : 2;
    extern __shared__ char smem[];
    const uint32_t sbase = smem_u32(smem);
    const int tid = threadIdx.x, lane = tid & 31, wid = tid >> 5;
    const int wm = (NTILE == 128) ? (wid & 1) : (wid & 3);
    const int wn = (NTILE == 128) ? (wid >> 1) : (wid >> 2);

    float acc[MI][4][4];
    #pragma unroll
    for (int i = 0; i < MI; ++i)
        #pragma unroll
        for (int j = 0; j < 4; ++j)
            #pragma unroll
            for (int v = 0; v < 4; ++v) acc[i][j][v] = 0.f;

    load_stage<NTILE>(sbase,            Ah, lda, Bh, ldb, 0);
    load_stage<NTILE>(sbase + L::STAGE, Ah, lda, Bh, ldb, 32);

    const int mi = lane >> 3, lr = lane & 7;
    const int rA0 = wm * (MI * 16) + (mi & 1) * 8 + lr;
    const int rB0 = wn * 32 + (mi & 1) * 8 + lr;
    const int chb = mi >> 1;

    for (int it = 0; it < kIters; ++it) {
        if (it + 1 < kIters)
            asm volatile("cp.async.wait_group 1;" ::: "memory");
        else
            asm volatile("cp.async.wait_group 0;" ::: "memory");
        __syncthreads();

        uint32_t sb = sbase + (uint32_t)(it % 3) * L::STAGE;
        if (it + 2 < kIters)
            load_stage<NTILE>(sbase + (uint32_t)((it + 2) % 3) * L::STAGE,
                              Ah, lda, Bh, ldb, (it + 2) * 32);

        #pragma unroll
        for (int kk = 0; kk < 2; ++kk) {
            int c = kk * 2 + chb;
            uint32_t a[MI][4], bh[2][4];
            #pragma unroll
            for (int j = 0; j < 2; ++j) {
                int r = rB0 + j * 16;
                ldsm4(bh[j], sb + L::BH + swz(r, c));
            }
            #pragma unroll
            for (int i = 0; i < MI; ++i) {
                int r = rA0 + i * 16;
                ldsm4(a[i], sb + swz(r, c));
            }
            #pragma unroll
            for (int i = 0; i < MI; ++i)
                #pragma unroll
                for (int j = 0; j < 4; ++j) {
                    int j2 = j >> 1, jo = j & 1;
                    mma16816(acc[i][j], a[i], bh[j2][jo], bh[j2][jo + 2]);
                }
        }
    }

    #pragma unroll
    for (int i = 0; i < MI; ++i)
        #pragma unroll
        for (int j = 0; j < 4; ++j) {
            int r   = wm * (MI * 16) + i * 16 + (lane >> 2);
            int col = wn * 32 + j * 8 + (lane & 3) * 2;
            if (EPI == 0) {
                atomicAdd(Cf + (size_t)r * ldc + col,           acc[i][j][0]);
                atomicAdd(Cf + (size_t)r * ldc + col + 1,       acc[i][j][1]);
                atomicAdd(Cf + (size_t)(r + 8) * ldc + col,     acc[i][j][2]);
                atomicAdd(Cf + (size_t)(r + 8) * ldc + col + 1, acc[i][j][3]);
            } else if (EPI == 1) {
                *reinterpret_cast<float2*>(Cf + (size_t)r * ldc + col) =
                    make_float2(acc[i][j][0], acc[i][j][1]);
                *reinterpret_cast<float2*>(Cf + (size_t)(r + 8) * ldc + col) =
                    make_float2(acc[i][j][2], acc[i][j][3]);
            } else {
                __half2 p0, p1;
                p0.x = __float2half_rn(acc[i][j][0]);
                p0.y = __float2half_rn(acc[i][j][1]);
                p1.x = __float2half_rn(acc[i][j][2]);
                p1.y = __float2half_rn(acc[i][j][3]);
                *reinterpret_cast<__half2*>(CH + (size_t)r * ldc + col)       = p0;
                *reinterpret_cast<__half2*>(CH + (size_t)(r + 8) * ldc + col) = p1;
            }
        }
}

// ---- pass wrappers ----
// p1: P = Xh^T Xh, upper 128-tiles only, split-K x8 over t
__global__ void __launch_bounds__(256, 2) k_p1() {
    int z = blockIdx.z, pair = z >> 3, split = z & 7;
    int m0 = blockIdx.x * 128, n0 = blockIdx.y * 128;
    if (m0 > n0) return;                   // symmetric: skip lower tile
    int b = pair >> 2, q = pair & 3;
    size_t base = ((size_t)b * HID + q * H) * SEQ + split * 256;
    const __half* A = g_hidTH + base + (size_t)m0 * SEQ;
    const __half* B = g_hidTH + base + (size_t)n0 * SEQ;
    gemm_mma<0, 128>(A, SEQ, B, SEQ, 8,
                     g_Pf + (size_t)pair * H * H + m0 * H + n0, nullptr, H);
}
// K (fp16) = P mirrored to full symmetric matrix
__global__ void __launch_bounds__(256) k_mirror() {
    __shared__ float sh[32][33];
    int pair = blockIdx.z, it = blockIdx.y, jt = blockIdx.x;
    int tx = threadIdx.x & 31, ty = threadIdx.x >> 5;
    const float* P = g_Pf + (size_t)pair * H * H;
    bool mirror = (it >> 2) > (jt >> 2);   // (1,0) 128-block not stored -> use (0,1)^T
    if (mirror) {
        #pragma unroll
        for (int i = 0; i < 4; ++i) {
            int r = ty + i * 8;
            sh[r][tx] = P[(size_t)(jt * 32 + r) * H + it * 32 + tx];
        }
    }
    __syncthreads();
    #pragma unroll
    for (int i = 0; i < 4; ++i) {
        int r = ty + i * 8;
        int row = it * 32 + r, col = jt * 32 + tx;
        float v = mirror ? sh[tx][r] : P[(size_t)row * H + col];
        g_KH[(size_t)pair * H * H + (size_t)row * H + col] = __float2half_rn(v);
    }
}
// p2: tmp = qw_h * Kh  (K symmetric), fp16 store
__global__ void __launch_bounds__(256, 2) k_p2() {
    int z = blockIdx.z, b = z >> 4, a = (z >> 2) & 3, q = z & 3;
    int m0 = blockIdx.x * 128, n0 = blockIdx.y * 64;
    size_t ab = (size_t)a * H * HID + (size_t)m0 * HID + q * H;
    size_t bb = (size_t)((b << 2) | q) * H * H + (size_t)n0 * H;
    size_t cb = (size_t)((b << 2) | a) * H * HID + (size_t)m0 * HID + q * H + n0;
    gemm_mma<2, 64>(g_qH + ab, HID, g_KH + bb, H, 8, nullptr, g_tmpH + cb, HID);
}
// p3: M^T = cT_h * tmpH^T, split-K x4
__global__ void __launch_bounds__(256, 2) k_p3() {
    int z = blockIdx.z, pair = z >> 2, split = z & 3;
    int a = pair & 3;
    int m0 = blockIdx.x * 128, n0 = blockIdx.y * 64;
    size_t ab = (size_t)a * H * HID + (size_t)m0 * HID + split * 256;
    size_t bb = (size_t)pair * H * HID + (size_t)n0 * HID + split * 256;
    gemm_mma<0, 64>(g_cTH + ab, HID, g_tmpH + bb, HID, 8,
                    g_Mf + (size_t)pair * H * H + m0 * H + n0, nullptr, H);
}
// convert M^T -> MH fp16
__global__ void __launch_bounds__(256) k_cvtM() {
    size_t i = (size_t)blockIdx.x * 2048 + threadIdx.x * 8;
    #pragma unroll
    for (int j = 0; j < 8; ++j)
        g_MH[i + j] = __float2half_rn(g_Mf[i + j]);
}
// p4: out = hid_h * Mh
__global__ void __launch_bounds__(256, 2) k_p4(float* __restrict__ out) {
    int pair = blockIdx.z, b = pair >> 2, a = pair & 3;
    int m0 = blockIdx.x * 128, n0 = blockIdx.y * 128;
    size_t ab = (size_t)b * SEQ * HID + (size_t)m0 * HID + a * H;
    size_t bb = (size_t)pair * H * H + (size_t)n0 * H;
    gemm_mma<1, 128>(g_hidH + ab, HID, g_MH + bb, H, 8, out + ab + n0, nullptr, HID);
}

// ---- merged prep ----
// [0,1024): hidden convert + transpose; [1024,2048): queries; [2048,3072): comb T;
// [3072,3328): zero Pf/Mf
__global__ void __launch_bounds__(256) k_prep(const float* __restrict__ hid,
                                              const float* __restrict__ q,
                                              const float* __restrict__ c) {
    int blk = blockIdx.x, tid = threadIdx.x;
    if (blk < 1024) {
        __shared__ __half shH[64][65];
        int b = blk >> 9, tt = (blk >> 4) & 31, ft = blk & 15;
        int w = tid >> 5, l = tid & 31;
        int t0 = tt * 64, f0 = ft * 64;
        #pragma unroll
        for (int i = 0; i < 8; ++i) {
            int r = w * 8 + i;
            size_t gi = ((size_t)b * SEQ + t0 + r) * HID + f0 + l * 2;
            float2 v = *reinterpret_cast<const float2*>(hid + gi);
            __half h0 = __float2half_rn(v.x), h1 = __float2half_rn(v.y);
            shH[r][l * 2] = h0; shH[r][l * 2 + 1] = h1;
            __half2 ph; ph.x = h0; ph.y = h1;
            *reinterpret_cast<__half2*>(g_hidH + gi) = ph;
        }
        __syncthreads();
        #pragma unroll
        for (int i = 0; i < 8; ++i) {
            int fr = w * 8 + i;
            size_t gi = ((size_t)b * HID + f0 + fr) * SEQ + t0 + l * 2;
            __half2 hv;
            hv.x = shH[l * 2][fr]; hv.y = shH[l * 2 + 1][fr];
            *reinterpret_cast<__half2*>(g_hidTH + gi) = hv;
        }
    } else if (blk < 2048) {
        size_t i = (size_t)(blk - 1024) * 1024 + tid * 4;
        float4 v = *reinterpret_cast<const float4*>(q + i);
        __half2 p0, p1;
        p0.x = __float2half_rn(v.x); p0.y = __float2half_rn(v.y);
        p1.x = __float2half_rn(v.z); p1.y = __float2half_rn(v.w);
        *reinterpret_cast<__half2*>(g_qH + i)     = p0;
        *reinterpret_cast<__half2*>(g_qH + i + 2) = p1;
    } else if (blk < 3072) {
        __shared__ __half sh[32][33];
        int z = blk - 2048;
        int a = z >> 8, kt = (z >> 3) & 31, gt = z & 7;
        int tx = tid & 31, ty = tid >> 5;
        int k0 = kt * 32, g0 = gt * 32;
        #pragma unroll
        for (int i = 0; i < 4; ++i) {
            int r = ty + i * 8;
            sh[r][tx] = __float2half_rn(c[((size_t)a * HID + k0 + r) * H + g0 + tx]);
        }
        __syncthreads();
        #pragma unroll
        for (int i = 0; i < 4; ++i) {
            int r = ty + i * 8;
            g_cTH[((size_t)a * H + g0 + r) * HID + k0 + tx] = sh[tx][r];
        }
    } else {
        int z = blk - 3072;                 // 0..255 : zero Pf, Mf
        float* dst = (z < 128) ? g_Pf : g_Mf;
        size_t base = (size_t)(z & 127) * 4096 + tid * 16;
        float4 zv = make_float4(0.f, 0.f, 0.f, 0.f);
        #pragma unroll
        for (int i = 0; i < 4; ++i)
            *reinterpret_cast<float4*>(dst + base + i * 4) = zv;
    }
}

extern "C" void kernel_launch(void* const* d_in, const int* in_sizes, int n_in,
                              void* d_out, int out_size) {
    const float* hidden    = (const float*)d_in[0];
    const float* queries   = (const float*)d_in[1];
    const float* combiners = (const float*)d_in[2];
    float* out = (float*)d_out;

    cudaFuncSetAttribute(k_p1, cudaFuncAttributeMaxDynamicSharedMemorySize, 49152);
    cudaFuncSetAttribute(k_p2, cudaFuncAttributeMaxDynamicSharedMemorySize, 36864);
    cudaFuncSetAttribute(k_p3, cudaFuncAttributeMaxDynamicSharedMemorySize, 36864);
    cudaFuncSetAttribute(k_p4, cudaFuncAttributeMaxDynamicSharedMemorySize, 49152);

    k_prep<<<3328, 256>>>(hidden, queries, combiners);
    k_p1<<<dim3(2, 2, 64), 256, 49152>>>();
    k_mirror<<<dim3(8, 8, 8), 256>>>();
    k_p2<<<dim3(2, 4, 32), 256, 36864>>>();
    k_p3<<<dim3(2, 4, 32), 256, 36864>>>();
    k_cvtM<<<256, 256>>>();
    k_p4<<<dim3(16, 2, 8), 256, 49152>>>(out);
}

// round 13
// speedup vs baseline: 1.9907x; 1.0056x over previous
#include <cuda_runtime.h>
#include <cuda_fp16.h>
#include <cstdint>

#define BSZ 2
#define SEQ 2048
#define HID 1024
#define NS  4
#define H   256

// ---------------- device scratch ----------------
__device__ __align__(256) __half g_hidH [BSZ*SEQ*HID];   // hidden hi, row-major
__device__ __align__(256) __half g_hidTH[BSZ*HID*SEQ];   // hidden hi, transposed
__device__ __align__(256) __half g_qH   [NS*H*HID];      // queries hi
__device__ __align__(256) __half g_cTH  [NS*H*HID];      // combiners^T hi
__device__ __align__(256) float  g_Pf   [8*H*H];         // Xh^T Xh (upper 128-tiles)
__device__ __align__(256) __half g_tmpH [8*H*HID];
__device__ __align__(256) float  g_Mf   [8*H*H];         // M^T

// ---------------- helpers ----------------
__device__ __forceinline__ uint32_t smem_u32(const void* p) {
    uint32_t a;
    asm("{ .reg .u64 t; cvta.to.shared.u64 t, %1; cvt.u32.u64 %0, t; }" : "=r"(a) : "l"(p));
    return a;
}
__device__ __forceinline__ void cpa(uint32_t dst, const void* src) {
    asm volatile("cp.async.cg.shared.global [%0], [%1], 16;" :: "r"(dst), "l"(src));
}
__device__ __forceinline__ void ldsm4(uint32_t (&r)[4], uint32_t addr) {
    asm volatile("ldmatrix.sync.aligned.m8n8.x4.shared.b16 {%0,%1,%2,%3}, [%4];"
        : "=r"(r[0]), "=r"(r[1]), "=r"(r[2]), "=r"(r[3]) : "r"(addr));
}
__device__ __forceinline__ void sts128(uint32_t addr, uint32_t x, uint32_t y,
                                       uint32_t z, uint32_t w) {
    asm volatile("st.shared.v4.b32 [%0], {%1, %2, %3, %4};"
        :: "r"(addr), "r"(x), "r"(y), "r"(z), "r"(w) : "memory");
}
__device__ __forceinline__ void mma16816(float (&d)[4], const uint32_t (&a)[4],
                                         uint32_t b0, uint32_t b1) {
    asm volatile("mma.sync.aligned.m16n8k16.row.col.f32.f16.f16.f32 "
        "{%0,%1,%2,%3}, {%4,%5,%6,%7}, {%8,%9}, {%0,%1,%2,%3};"
        : "+f"(d[0]), "+f"(d[1]), "+f"(d[2]), "+f"(d[3])
        : "r"(a[0]), "r"(a[1]), "r"(a[2]), "r"(a[3]), "r"(b0), "r"(b1));
}
__device__ __forceinline__ uint32_t swz(int row, int c) {
    return (uint32_t)(row * 64 + ((c ^ ((row >> 1) & 3)) << 4));
}

// Stage layout: Ah[128x32] @0 (8KB), B[NTILE x 32] fp16 after
template<int NTILE> struct Lay {
    static constexpr uint32_t BH = 8192u;
    static constexpr uint32_t BN = (NTILE == 128) ? 8192u : 4096u;
    static constexpr uint32_t STAGE = BH + BN;
};

// A-only cp.async stage load (A[128 x 32] fp16)
__device__ __forceinline__ void load_stageA(uint32_t sb,
        const __half* __restrict__ Ah, int lda, int k0) {
    int tid = threadIdx.x;
    #pragma unroll
    for (int t = 0; t < 2; ++t) {
        int cid = tid + t * 256;
        int row = cid >> 2, c = cid & 3;
        cpa(sb + swz(row, c), Ah + (size_t)row * lda + k0 + c * 8);
    }
    asm volatile("cp.async.commit_group;" ::: "memory");
}
// A+B cp.async stage load (B fp16 source)
template<int NTILE>
__device__ __forceinline__ void load_stageAB(uint32_t sb,
        const __half* __restrict__ Ah, int lda,
        const __half* __restrict__ Bh, int ldb, int k0) {
    using L = Lay<NTILE>;
    int tid = threadIdx.x;
    #pragma unroll
    for (int t = 0; t < 2; ++t) {
        int cid = tid + t * 256;
        int row = cid >> 2, c = cid & 3;
        cpa(sb + swz(row, c), Ah + (size_t)row * lda + k0 + c * 8);
    }
    if (NTILE == 128) {
        #pragma unroll
        for (int t = 0; t < 2; ++t) {
            int cid = tid + t * 256;
            int row = cid >> 2, c = cid & 3;
            cpa(sb + L::BH + swz(row, c), Bh + (size_t)row * ldb + k0 + c * 8);
        }
    } else {
        int row = tid >> 2, c = tid & 3;
        cpa(sb + L::BH + swz(row, c), Bh + (size_t)row * ldb + k0 + c * 8);
    }
    asm volatile("cp.async.commit_group;" ::: "memory");
}

// fp32 B gather into regs. MIRROR: symmetric source (upper 128-tiles stored)
template<int NTILE, bool MIRROR>
__device__ __forceinline__ void ldgB(float* rB, const float* __restrict__ Bf,
                                     int n0g, int kg0) {
    int tid = threadIdx.x;
    #pragma unroll
    for (int t = 0; t < NTILE / 64; ++t) {
        int cid = tid + t * 256;
        int r = cid >> 2, c = cid & 3;
        int gn = n0g + r, gk = kg0 + c * 8;
        float* d = rB + t * 8;
        if (MIRROR && (gn >> 7) > (gk >> 7)) {
            #pragma unroll
            for (int j = 0; j < 8; ++j)
                d[j] = Bf[(size_t)(gk + j) * H + gn];
        } else {
            *reinterpret_cast<float4*>(d) =
                *reinterpret_cast<const float4*>(Bf + (size_t)gn * H + gk);
            *reinterpret_cast<float4*>(d + 4) =
                *reinterpret_cast<const float4*>(Bf + (size_t)gn * H + gk + 4);
        }
    }
}
// convert + store B regs into swizzled fp16 stage region (shared-space store)
template<int NTILE>
__device__ __forceinline__ void stsB(uint32_t sbB, const float* rB) {
    int tid = threadIdx.x;
    #pragma unroll
    for (int t = 0; t < NTILE / 64; ++t) {
        int cid = tid + t * 256;
        int r = cid >> 2, c = cid & 3;
        const float* s = rB + t * 8;
        __half2 h0, h1, h2, h3;
        h0.x = __float2half_rn(s[0]); h0.y = __float2half_rn(s[1]);
        h1.x = __float2half_rn(s[2]); h1.y = __float2half_rn(s[3]);
        h2.x = __float2half_rn(s[4]); h2.y = __float2half_rn(s[5]);
        h3.x = __float2half_rn(s[6]); h3.y = __float2half_rn(s[7]);
        sts128(sbB + swz(r, c),
               *reinterpret_cast<uint32_t*>(&h0),
               *reinterpret_cast<uint32_t*>(&h1),
               *reinterpret_cast<uint32_t*>(&h2),
               *reinterpret_cast<uint32_t*>(&h3));
    }
}

// C[128,NTILE] = Ah[128,K] * B[NTILE,K]^T   (fp16, fp32 accum)
// BSRC: 0 = B fp16 cp.async; 1 = B fp32 convert; 2 = fp32 convert + sym mirror
// EPI:  0 = atomicAdd fp32, 1 = store fp32, 2 = store fp16
template<int EPI, int NTILE, int BSRC>
__device__ void gemm_mma(const __half* Ah, int lda,
                         const __half* Bh, int ldb,
                         const float* Bf, int n0g, int kIters,
                         float* Cf, __half* CH, int ldc) {
    using L = Lay<NTILE>;
    constexpr int MI = (NTILE == 128) ? 4 : 2;
    extern __shared__ char smem[];
    const uint32_t sbase = smem_u32(smem);
    const int tid = threadIdx.x, lane = tid & 31, wid = tid >> 5;
    const int wm = (NTILE == 128) ? (wid & 1) : (wid & 3);
    const int wn = (NTILE == 128) ? (wid >> 1) : (wid >> 2);

    float acc[MI][4][4];
    #pragma unroll
    for (int i = 0; i < MI; ++i)
        #pragma unroll
        for (int j = 0; j < 4; ++j)
            #pragma unroll
            for (int v = 0; v < 4; ++v) acc[i][j][v] = 0.f;

    float rB[(BSRC == 0) ? 1 : (NTILE / 64) * 8];
    if (BSRC == 0) {
        load_stageAB<NTILE>(sbase,            Ah, lda, Bh, ldb, 0);
        load_stageAB<NTILE>(sbase + L::STAGE, Ah, lda, Bh, ldb, 32);
    } else {
        load_stageA(sbase,            Ah, lda, 0);
        load_stageA(sbase + L::STAGE, Ah, lda, 32);
        ldgB<NTILE, BSRC == 2>(rB, Bf, n0g, 0);
    }

    const int mi = lane >> 3, lr = lane & 7;
    const int rA0 = wm * (MI * 16) + (mi & 1) * 8 + lr;
    const int rB0 = wn * 32 + (mi & 1) * 8 + lr;
    const int chb = mi >> 1;

    for (int it = 0; it < kIters; ++it) {
        if (it + 1 < kIters)
            asm volatile("cp.async.wait_group 1;" ::: "memory");
        else
            asm volatile("cp.async.wait_group 0;" ::: "memory");
        uint32_t sb = sbase + (uint32_t)(it % 3) * L::STAGE;
        if (BSRC != 0)
            stsB<NTILE>(sb + L::BH, rB);
        __syncthreads();

        if (it + 2 < kIters) {
            if (BSRC == 0)
                load_stageAB<NTILE>(sbase + (uint32_t)((it + 2) % 3) * L::STAGE,
                                    Ah, lda, Bh, ldb, (it + 2) * 32);
            else
                load_stageA(sbase + (uint32_t)((it + 2) % 3) * L::STAGE,
                            Ah, lda, (it + 2) * 32);
        }
        if (BSRC != 0 && it + 1 < kIters)
            ldgB<NTILE, BSRC == 2>(rB, Bf, n0g, (it + 1) * 32);

        #pragma unroll
        for (int kk = 0; kk < 2; ++kk) {
            int c = kk * 2 + chb;
            uint32_t a[MI][4], bfr[2][4];
            #pragma unroll
            for (int j = 0; j < 2; ++j) {
                int r = rB0 + j * 16;
                ldsm4(bfr[j], sb + L::BH + swz(r, c));
            }
            #pragma unroll
            for (int i = 0; i < MI; ++i) {
                int r = rA0 + i * 16;
                ldsm4(a[i], sb + swz(r, c));
            }
            #pragma unroll
            for (int i = 0; i < MI; ++i)
                #pragma unroll
                for (int j = 0; j < 4; ++j) {
                    int j2 = j >> 1, jo = j & 1;
                    mma16816(acc[i][j], a[i], bfr[j2][jo], bfr[j2][jo + 2]);
                }
        }
    }

    #pragma unroll
    for (int i = 0; i < MI; ++i)
        #pragma unroll
        for (int j = 0; j < 4; ++j) {
            int r   = wm * (MI * 16) + i * 16 + (lane >> 2);
            int col = wn * 32 + j * 8 + (lane & 3) * 2;
            if (EPI == 0) {
                atomicAdd(Cf + (size_t)r * ldc + col,           acc[i][j][0]);
                atomicAdd(Cf + (size_t)r * ldc + col + 1,       acc[i][j][1]);
                atomicAdd(Cf + (size_t)(r + 8) * ldc + col,     acc[i][j][2]);
                atomicAdd(Cf + (size_t)(r + 8) * ldc + col + 1, acc[i][j][3]);
            } else if (EPI == 1) {
                *reinterpret_cast<float2*>(Cf + (size_t)r * ldc + col) =
                    make_float2(acc[i][j][0], acc[i][j][1]);
                *reinterpret_cast<float2*>(Cf + (size_t)(r + 8) * ldc + col) =
                    make_float2(acc[i][j][2], acc[i][j][3]);
            } else {
                __half2 p0, p1;
                p0.x = __float2half_rn(acc[i][j][0]);
                p0.y = __float2half_rn(acc[i][j][1]);
                p1.x = __float2half_rn(acc[i][j][2]);
                p1.y = __float2half_rn(acc[i][j][3]);
                *reinterpret_cast<__half2*>(CH + (size_t)r * ldc + col)       = p0;
                *reinterpret_cast<__half2*>(CH + (size_t)(r + 8) * ldc + col) = p1;
            }
        }
}

// ---- pass wrappers ----
// p1: P = Xh^T Xh, 3 live tiles, split-K x8 over t
__global__ void __launch_bounds__(256, 2) k_p1() {
    int z = blockIdx.z, pair = z >> 3, split = z & 7;
    int m0 = (blockIdx.x == 2) ? 128 : 0;
    int n0 = (blockIdx.x == 0) ? 0 : 128;
    int b = pair >> 2, q = pair & 3;
    size_t base = ((size_t)b * HID + q * H) * SEQ + split * 256;
    const __half* A = g_hidTH + base + (size_t)m0 * SEQ;
    const __half* B = g_hidTH + base + (size_t)n0 * SEQ;
    gemm_mma<0, 128, 0>(A, SEQ, B, SEQ, nullptr, 0, 8,
                        g_Pf + (size_t)pair * H * H + m0 * H + n0, nullptr, H);
}
// p2: tmp = qw_h * K  (K = sym(P), fp32 source w/ fused mirror+convert)
__global__ void __launch_bounds__(256, 2) k_p2() {
    int z = blockIdx.z, b = z >> 4, a = (z >> 2) & 3, q = z & 3;
    int m0 = blockIdx.x * 128, n0 = blockIdx.y * 64;
    size_t ab = (size_t)a * H * HID + (size_t)m0 * HID + q * H;
    size_t cb = (size_t)((b << 2) | a) * H * HID + (size_t)m0 * HID + q * H + n0;
    const float* Bf = g_Pf + (size_t)((b << 2) | q) * H * H;
    gemm_mma<2, 64, 2>(g_qH + ab, HID, nullptr, 0, Bf, n0, 8,
                       nullptr, g_tmpH + cb, HID);
}
// p3: M^T = cT_h * tmpH^T, split-K x4 (B fp16 cp.async)
__global__ void __launch_bounds__(256, 2) k_p3() {
    int z = blockIdx.z, pair = z >> 2, split = z & 3;
    int a = pair & 3;
    int m0 = blockIdx.x * 128, n0 = blockIdx.y * 64;
    size_t ab = (size_t)a * H * HID + (size_t)m0 * HID + split * 256;
    size_t bb = (size_t)pair * H * HID + (size_t)n0 * HID + split * 256;
    gemm_mma<0, 64, 0>(g_cTH + ab, HID, g_tmpH + bb, HID, nullptr, 0, 8,
                       g_Mf + (size_t)pair * H * H + m0 * H + n0, nullptr, H);
}
// p4: out = hid_h * M  (M fp32 source w/ fused convert)
__global__ void __launch_bounds__(256, 2) k_p4(float* __restrict__ out) {
    int pair = blockIdx.z, b = pair >> 2, a = pair & 3;
    int m0 = blockIdx.x * 128, n0 = blockIdx.y * 128;
    size_t ab = (size_t)b * SEQ * HID + (size_t)m0 * HID + a * H;
    const float* Bf = g_Mf + (size_t)pair * H * H;
    gemm_mma<1, 128, 1>(g_hidH + ab, HID, nullptr, 0, Bf, n0, 8,
                        out + ab + n0, nullptr, HID);
}

// ---- merged prep ----
// [0,1024): hidden convert + transpose; [1024,2048): queries; [2048,3072): comb T;
// [3072,3328): zero Pf/Mf
__global__ void __launch_bounds__(256) k_prep(const float* __restrict__ hid,
                                              const float* __restrict__ q,
                                              const float* __restrict__ c) {
    int blk = blockIdx.x, tid = threadIdx.x;
    if (blk < 1024) {
        __shared__ __half shH[64][65];
        int b = blk >> 9, tt = (blk >> 4) & 31, ft = blk & 15;
        int w = tid >> 5, l = tid & 31;
        int t0 = tt * 64, f0 = ft * 64;
        #pragma unroll
        for (int i = 0; i < 8; ++i) {
            int r = w * 8 + i;
            size_t gi = ((size_t)b * SEQ + t0 + r) * HID + f0 + l * 2;
            float2 v = *reinterpret_cast<const float2*>(hid + gi);
            __half h0 = __float2half_rn(v.x), h1 = __float2half_rn(v.y);
            shH[r][l * 2] = h0; shH[r][l * 2 + 1] = h1;
            __half2 ph; ph.x = h0; ph.y = h1;
            *reinterpret_cast<__half2*>(g_hidH + gi) = ph;
        }
        __syncthreads();
        #pragma unroll
        for (int i = 0; i < 8; ++i) {
            int fr = w * 8 + i;
            size_t gi = ((size_t)b * HID + f0 + fr) * SEQ + t0 + l * 2;
            __half2 hv;
            hv.x = shH[l * 2][fr]; hv.y = shH[l * 2 + 1][fr];
            *reinterpret_cast<__half2*>(g_hidTH + gi) = hv;
        }
    } else if (blk < 2048) {
        size_t i = (size_t)(blk - 1024) * 1024 + tid * 4;
        float4 v = *reinterpret_cast<const float4*>(q + i);
        __half2 p0, p1;
        p0.x = __float2half_rn(v.x); p0.y = __float2half_rn(v.y);
        p1.x = __float2half_rn(v.z); p1.y = __float2half_rn(v.w);
        *reinterpret_cast<__half2*>(g_qH + i)     = p0;
        *reinterpret_cast<__half2*>(g_qH + i + 2) = p1;
    } else if (blk < 3072) {
        __shared__ __half sh[32][33];
        int z = blk - 2048;
        int a = z >> 8, kt = (z >> 3) & 31, gt = z & 7;
        int tx = tid & 31, ty = tid >> 5;
        int k0 = kt * 32, g0 = gt * 32;
        #pragma unroll
        for (int i = 0; i < 4; ++i) {
            int r = ty + i * 8;
            sh[r][tx] = __float2half_rn(c[((size_t)a * HID + k0 + r) * H + g0 + tx]);
        }
        __syncthreads();
        #pragma unroll
        for (int i = 0; i < 4; ++i) {
            int r = ty + i * 8;
            g_cTH[((size_t)a * H + g0 + r) * HID + k0 + tx] = sh[tx][r];
        }
    } else {
        int z = blk - 3072;                 // 0..255 : zero Pf, Mf
        float* dst = (z < 128) ? g_Pf : g_Mf;
        size_t base = (size_t)(z & 127) * 4096 + tid * 16;
        float4 zv = make_float4(0.f, 0.f, 0.f, 0.f);
        #pragma unroll
        for (int i = 0; i < 4; ++i)
            *reinterpret_cast<float4*>(dst + base + i * 4) = zv;
    }
}

extern "C" void kernel_launch(void* const* d_in, const int* in_sizes, int n_in,
                              void* d_out, int out_size) {
    const float* hidden    = (const float*)d_in[0];
    const float* queries   = (const float*)d_in[1];
    const float* combiners = (const float*)d_in[2];
    float* out = (float*)d_out;

    cudaFuncSetAttribute(k_p1, cudaFuncAttributeMaxDynamicSharedMemorySize, 49152);
    cudaFuncSetAttribute(k_p2, cudaFuncAttributeMaxDynamicSharedMemorySize, 36864);
    cudaFuncSetAttribute(k_p3, cudaFuncAttributeMaxDynamicSharedMemorySize, 36864);
    cudaFuncSetAttribute(k_p4, cudaFuncAttributeMaxDynamicSharedMemorySize, 49152);

    k_prep<<<3328, 256>>>(hidden, queries, combiners);
    k_p1<<<dim3(3, 1, 64), 256, 49152>>>();
    k_p2<<<dim3(2, 4, 32), 256, 36864>>>();
    k_p3<<<dim3(2, 4, 32), 256, 36864>>>();
    k_p4<<<dim3(16, 2, 8), 256, 49152>>>(out);
}